// round 5
// baseline (speedup 1.0000x reference)
#include <cuda_runtime.h>
#include <cuda_fp16.h>

#define NN   50000
#define NE   800000
#define KIN  256
#define MOUT 128
#define NH   4

// Scratch (allocation-free rule: __device__ globals)
__device__ __align__(16) __half g_Wx_h[NN * MOUT];  // 12.8 MB fp16 Wx for agg
__device__ __align__(16) float g_ssrc[NN * NH];
__device__ __align__(16) float g_sdst[NN * NH];
__device__ int g_cnt[NN];
__device__ int g_off[NN + 1];
__device__ int g_cur[NN];
__device__ int g_esrc[NE];

// ---------------------------------------------------------------------------
// CSR build (runs on side stream, overlapped with GEMM)
// ---------------------------------------------------------------------------
__global__ void zero2_kernel() {
    int i = blockIdx.x * blockDim.x + threadIdx.x;
    if (i < NN) { g_cnt[i] = 0; g_cur[i] = 0; }
}

__global__ void hist_kernel(const int* __restrict__ ei) {
    int e = blockIdx.x * blockDim.x + threadIdx.x;
    if (e < NE) atomicAdd(&g_cnt[ei[NE + e]], 1);
}

// Single-block exclusive scan of g_cnt -> g_off (1024 threads, 49 elems each)
__global__ __launch_bounds__(1024) void scan_kernel() {
    __shared__ int wsum[32];
    const int C = 49;                       // 1024*49 = 50176 >= NN
    int t = threadIdx.x;
    int lane = t & 31;
    int wid = t >> 5;
    int p = t * C;

    int sum = 0;
    #pragma unroll 7
    for (int j = 0; j < C; j++) {
        int i = p + j;
        if (i < NN) sum += g_cnt[i];
    }

    // inclusive warp scan
    int inc = sum;
    #pragma unroll
    for (int o = 1; o < 32; o <<= 1) {
        int v = __shfl_up_sync(0xffffffffu, inc, o);
        if (lane >= o) inc += v;
    }
    if (lane == 31) wsum[wid] = inc;
    __syncthreads();
    if (wid == 0) {
        int v = (lane < 32) ? wsum[lane] : 0;
        int wi = v;
        #pragma unroll
        for (int o = 1; o < 32; o <<= 1) {
            int u = __shfl_up_sync(0xffffffffu, wi, o);
            if (lane >= o) wi += u;
        }
        wsum[lane] = wi - v;   // exclusive warp base
    }
    __syncthreads();

    int run = wsum[wid] + inc - sum;        // exclusive base for this thread
    #pragma unroll 7
    for (int j = 0; j < C; j++) {
        int i = p + j;
        if (i < NN) {
            g_off[i] = run;
            run += g_cnt[i];
        }
    }
    if (t == 0) g_off[NN] = NE;
}

__global__ void fill_kernel(const int* __restrict__ ei) {
    int e = blockIdx.x * blockDim.x + threadIdx.x;
    if (e >= NE) return;
    int s = ei[e];
    int d = ei[NE + e];
    int pos = g_off[d] + atomicAdd(&g_cur[d], 1);
    g_esrc[pos] = s;
}

// ---------------------------------------------------------------------------
// tf32 tensor-core GEMM: Wx = x @ W^T, 128x128 block tile, 8 warps (4x2),
// warp = 32x64 = 2x8 m16n8k8 tiles. Fused fp16 Wx store + per-head scores.
// ---------------------------------------------------------------------------
#define BMT 128
#define BKT 32
#define XPAD 36

__device__ __forceinline__ unsigned f2tf32(float f) {
    unsigned u;
    asm("cvt.rna.tf32.f32 %0, %1;" : "=r"(u) : "f"(f));
    return u;
}

__device__ __forceinline__ void mma_tf32(float* c, const unsigned* a,
                                         unsigned b0, unsigned b1) {
    asm volatile(
        "mma.sync.aligned.m16n8k8.row.col.f32.tf32.tf32.f32 "
        "{%0,%1,%2,%3}, {%4,%5,%6,%7}, {%8,%9}, {%0,%1,%2,%3};"
        : "+f"(c[0]), "+f"(c[1]), "+f"(c[2]), "+f"(c[3])
        : "r"(a[0]), "r"(a[1]), "r"(a[2]), "r"(a[3]), "r"(b0), "r"(b1));
}

__global__ __launch_bounds__(256, 2)
void gemm_tf32_kernel(const float* __restrict__ x,
                      const float* __restrict__ W,
                      const float* __restrict__ aw) {
    __shared__ unsigned Xs[BMT * XPAD];
    __shared__ unsigned Ws[MOUT * XPAD];

    int tid  = threadIdx.x;
    int lane = tid & 31;
    int warp = tid >> 5;
    int g = lane >> 2;
    int t = lane & 3;
    int wm = warp & 3;
    int wn = warp >> 2;
    int row0 = blockIdx.x * BMT;

    float c[2][8][4];
    #pragma unroll
    for (int tm = 0; tm < 2; tm++)
        #pragma unroll
        for (int tn = 0; tn < 8; tn++)
            #pragma unroll
            for (int i = 0; i < 4; i++) c[tm][tn][i] = 0.f;

    for (int k0 = 0; k0 < KIN; k0 += BKT) {
        #pragma unroll
        for (int j = 0; j < 4; j++) {
            int idx = tid + 256 * j;
            int m   = idx >> 3;
            int kv  = (idx & 7) * 4;
            int row = row0 + m;
            float4 v = make_float4(0.f, 0.f, 0.f, 0.f);
            if (row < NN) v = *(const float4*)&x[row * KIN + k0 + kv];
            uint4 u;
            u.x = f2tf32(v.x); u.y = f2tf32(v.y);
            u.z = f2tf32(v.z); u.w = f2tf32(v.w);
            *(uint4*)&Xs[m * XPAD + kv] = u;

            float4 w4 = *(const float4*)&W[m * KIN + k0 + kv];
            uint4 uw;
            uw.x = f2tf32(w4.x); uw.y = f2tf32(w4.y);
            uw.z = f2tf32(w4.z); uw.w = f2tf32(w4.w);
            *(uint4*)&Ws[m * XPAD + kv] = uw;
        }
        __syncthreads();

        #pragma unroll
        for (int kk = 0; kk < BKT; kk += 8) {
            unsigned a[2][4];
            #pragma unroll
            for (int tm = 0; tm < 2; tm++) {
                int r = wm * 32 + tm * 16 + g;
                a[tm][0] = Xs[r * XPAD + kk + t];
                a[tm][1] = Xs[(r + 8) * XPAD + kk + t];
                a[tm][2] = Xs[r * XPAD + kk + t + 4];
                a[tm][3] = Xs[(r + 8) * XPAD + kk + t + 4];
            }
            #pragma unroll
            for (int tn = 0; tn < 8; tn++) {
                int n = wn * 64 + tn * 8 + g;
                unsigned b0 = Ws[n * XPAD + kk + t];
                unsigned b1 = Ws[n * XPAD + kk + t + 4];
                mma_tf32(c[0][tn], a[0], b0, b1);
                mma_tf32(c[1][tn], a[1], b0, b1);
            }
        }
        __syncthreads();
    }

    float as_r[4][2], ad_r[4][2];
    #pragma unroll
    for (int q = 0; q < 4; q++)
        #pragma unroll
        for (int j = 0; j < 2; j++) {
            as_r[q][j] = aw[q * 8 + 2 * t + j];
            ad_r[q][j] = aw[32 + q * 8 + 2 * t + j];
        }

    #pragma unroll
    for (int tm = 0; tm < 2; tm++)
    #pragma unroll
    for (int half = 0; half < 2; half++) {
        int row = row0 + wm * 32 + tm * 16 + half * 8 + g;

        if (row < NN) {
            #pragma unroll
            for (int tn = 0; tn < 8; tn++) {
                __half2 hv = __floats2half2_rn(c[tm][tn][half * 2],
                                               c[tm][tn][half * 2 + 1]);
                *(__half2*)&g_Wx_h[row * MOUT + wn * 64 + tn * 8 + 2 * t] = hv;
            }
        }

        #pragma unroll
        for (int hl = 0; hl < 2; hl++) {
            float ps = 0.f, pd = 0.f;
            #pragma unroll
            for (int q = 0; q < 4; q++)
                #pragma unroll
                for (int j = 0; j < 2; j++) {
                    float v = c[tm][hl * 4 + q][half * 2 + j];
                    ps += v * as_r[q][j];
                    pd += v * ad_r[q][j];
                }
            ps += __shfl_xor_sync(0xffffffffu, ps, 1);
            ps += __shfl_xor_sync(0xffffffffu, ps, 2);
            pd += __shfl_xor_sync(0xffffffffu, pd, 1);
            pd += __shfl_xor_sync(0xffffffffu, pd, 2);
            if (t == 0 && row < NN) {
                g_ssrc[row * NH + wn * 2 + hl] = ps;
                g_sdst[row * NH + wn * 2 + hl] = pd;
            }
        }
    }
}

// ---------------------------------------------------------------------------
// Aggregation: warp per dst node, smem alpha cache, fp16 gather, fused ELU.
// ---------------------------------------------------------------------------
#define CAP 64

__device__ __forceinline__ float lrelu_exp(float v) {
    float r = v > 0.f ? v : 0.2f * v;
    return __expf(r);
}

__global__ __launch_bounds__(256)
void agg_kernel(float* __restrict__ out) {
    __shared__ float s_al[8][CAP][4];   // 8 KB: per-warp edge numerators

    int w = threadIdx.x >> 5;
    int d = blockIdx.x * 8 + w;
    if (d >= NN) return;
    int lane = threadIdx.x & 31;
    int beg = g_off[d];
    int end = g_off[d + 1];
    int deg = end - beg;

    float4 sd4 = *(const float4*)&g_sdst[d * 4];

    // Pass 1: numerators -> smem cache + denom reduction
    float4 dn = make_float4(0.f, 0.f, 0.f, 0.f);
    for (int j = lane; j < deg; j += 32) {
        int s = g_esrc[beg + j];
        float4 a = *(const float4*)&g_ssrc[s * 4];
        float4 e;
        e.x = lrelu_exp(a.x + sd4.x);
        e.y = lrelu_exp(a.y + sd4.y);
        e.z = lrelu_exp(a.z + sd4.z);
        e.w = lrelu_exp(a.w + sd4.w);
        dn.x += e.x; dn.y += e.y; dn.z += e.z; dn.w += e.w;
        if (j < CAP) *(float4*)&s_al[w][j][0] = e;
    }
    #pragma unroll
    for (int m = 16; m; m >>= 1) {
        dn.x += __shfl_xor_sync(0xffffffffu, dn.x, m);
        dn.y += __shfl_xor_sync(0xffffffffu, dn.y, m);
        dn.z += __shfl_xor_sync(0xffffffffu, dn.z, m);
        dn.w += __shfl_xor_sync(0xffffffffu, dn.w, m);
    }
    __syncwarp();

    int h = lane >> 3;
    float dnh = (h == 0) ? dn.x : (h == 1) ? dn.y : (h == 2) ? dn.z : dn.w;
    float adh = (h == 0) ? sd4.x : (h == 1) ? sd4.y : (h == 2) ? sd4.z : sd4.w;
    float invd = __fdividef(1.f, dnh + 1e-8f);

    // Pass 2: fp16 weighted gather
    float4 acc = make_float4(0.f, 0.f, 0.f, 0.f);
    #pragma unroll 4
    for (int j = 0; j < deg; j++) {
        int s = g_esrc[beg + j];                         // warp-uniform, L1-hot
        float al;
        if (j < CAP) al = s_al[w][j][h] * invd;
        else         al = lrelu_exp(g_ssrc[s * 4 + h] + adh) * invd;
        float2 raw = *(const float2*)&g_Wx_h[s * MOUT + lane * 4];
        __half2 h01 = ((__half2*)&raw)[0];
        __half2 h23 = ((__half2*)&raw)[1];
        float2 f01 = __half22float2(h01);
        float2 f23 = __half22float2(h23);
        acc.x += al * f01.x; acc.y += al * f01.y;
        acc.z += al * f23.x; acc.w += al * f23.y;
    }

    acc.x = acc.x > 0.f ? acc.x : expm1f(acc.x);
    acc.y = acc.y > 0.f ? acc.y : expm1f(acc.y);
    acc.z = acc.z > 0.f ? acc.z : expm1f(acc.z);
    acc.w = acc.w > 0.f ? acc.w : expm1f(acc.w);
    *(float4*)&out[d * MOUT + lane * 4] = acc;
}

// ---------------------------------------------------------------------------
// Launch: GEMM on main stream, CSR build forked onto a side stream, join
// before agg. Fork/join via events -> parallel branches in the captured graph.
// ---------------------------------------------------------------------------
extern "C" void kernel_launch(void* const* d_in, const int* in_sizes, int n_in,
                              void* d_out, int out_size) {
    const float* x  = (const float*)d_in[0];
    const int*   ei = (const int*)d_in[1];
    const float* W  = (const float*)d_in[2];
    const float* aw = (const float*)d_in[3];
    float* out = (float*)d_out;

    cudaStream_t s;
    cudaStreamCreateWithFlags(&s, cudaStreamNonBlocking);
    cudaEvent_t eF, eJ;
    cudaEventCreateWithFlags(&eF, cudaEventDisableTiming);
    cudaEventCreateWithFlags(&eJ, cudaEventDisableTiming);

    // fork
    cudaEventRecord(eF, 0);
    cudaStreamWaitEvent(s, eF, 0);

    // side stream: CSR build
    zero2_kernel<<<(NN + 1023) / 1024, 1024, 0, s>>>();
    hist_kernel<<<(NE + 255) / 256, 256, 0, s>>>(ei);
    scan_kernel<<<1, 1024, 0, s>>>();
    fill_kernel<<<(NE + 255) / 256, 256, 0, s>>>(ei);
    cudaEventRecord(eJ, s);

    // main stream: GEMM (+ scores)
    gemm_tf32_kernel<<<(NN + BMT - 1) / BMT, 256>>>(x, W, aw);

    // join, then aggregate
    cudaStreamWaitEvent(0, eJ, 0);
    agg_kernel<<<(NN + 7) / 8, 256>>>(out);
}

// round 6
// speedup vs baseline: 1.0237x; 1.0237x over previous
#include <cuda_runtime.h>
#include <cuda_fp16.h>

#define NN   50000
#define NE   800000
#define KIN  256
#define MOUT 128
#define NH   4

// Scratch (allocation-free rule: __device__ globals)
__device__ __align__(16) __half g_Wx_h[NN * MOUT];  // 12.8 MB fp16 Wx for agg
__device__ __align__(16) float g_ssrc[NN * NH];
__device__ __align__(16) float g_sdst[NN * NH];
__device__ int g_cnt[NN];
__device__ int g_off[NN + 1];
__device__ int g_cur[NN];
__device__ int g_esrc[NE];

// ---------------------------------------------------------------------------
// CSR build
// ---------------------------------------------------------------------------
__global__ void zero2_kernel() {
    int i = blockIdx.x * blockDim.x + threadIdx.x;
    if (i < NN) { g_cnt[i] = 0; g_cur[i] = 0; }
}

__global__ void hist_kernel(const int* __restrict__ ei) {
    int e = blockIdx.x * blockDim.x + threadIdx.x;
    if (e < NE) atomicAdd(&g_cnt[ei[NE + e]], 1);
}

// Single-block exclusive scan of g_cnt -> g_off (1024 threads, 49 elems each)
__global__ __launch_bounds__(1024) void scan_kernel() {
    __shared__ int wsum[32];
    const int C = 49;                       // 1024*49 = 50176 >= NN
    int t = threadIdx.x;
    int lane = t & 31;
    int wid = t >> 5;
    int p = t * C;

    int sum = 0;
    #pragma unroll 7
    for (int j = 0; j < C; j++) {
        int i = p + j;
        if (i < NN) sum += g_cnt[i];
    }

    // inclusive warp scan of per-thread sums
    int inc = sum;
    #pragma unroll
    for (int o = 1; o < 32; o <<= 1) {
        int v = __shfl_up_sync(0xffffffffu, inc, o);
        if (lane >= o) inc += v;
    }
    if (lane == 31) wsum[wid] = inc;
    __syncthreads();
    if (wid == 0) {
        int v = (lane < 32) ? wsum[lane] : 0;
        int wi = v;
        #pragma unroll
        for (int o = 1; o < 32; o <<= 1) {
            int u = __shfl_up_sync(0xffffffffu, wi, o);
            if (lane >= o) wi += u;
        }
        wsum[lane] = wi - v;   // exclusive warp base
    }
    __syncthreads();

    int run = wsum[wid] + inc - sum;        // exclusive base for this thread
    #pragma unroll 7
    for (int j = 0; j < C; j++) {
        int i = p + j;
        if (i < NN) {
            g_off[i] = run;
            run += g_cnt[i];
        }
    }
    if (t == 0) g_off[NN] = NE;
}

// 2 edges per thread for MLP on the off-load -> atomic -> store chain
__global__ void fill_kernel(const int* __restrict__ ei) {
    int b = (blockIdx.x * blockDim.x + threadIdx.x) * 2;
    if (b >= NE) return;
    int s0 = ei[b];
    int d0 = ei[NE + b];
    int p0 = g_off[d0] + atomicAdd(&g_cur[d0], 1);
    if (b + 1 < NE) {
        int s1 = ei[b + 1];
        int d1 = ei[NE + b + 1];
        int p1 = g_off[d1] + atomicAdd(&g_cur[d1], 1);
        g_esrc[p1] = s1;
    }
    g_esrc[p0] = s0;
}

// ---------------------------------------------------------------------------
// tf32 tensor-core GEMM: Wx = x @ W^T, 128x128 block tile, 8 warps (4x2),
// warp = 32x64 = 2x8 m16n8k8 tiles. Fused fp16 Wx store + per-head scores.
// ---------------------------------------------------------------------------
#define BMT 128
#define BKT 32
#define XPAD 36

__device__ __forceinline__ unsigned f2tf32(float f) {
    unsigned u;
    asm("cvt.rna.tf32.f32 %0, %1;" : "=r"(u) : "f"(f));
    return u;
}

__device__ __forceinline__ void mma_tf32(float* c, const unsigned* a,
                                         unsigned b0, unsigned b1) {
    asm volatile(
        "mma.sync.aligned.m16n8k8.row.col.f32.tf32.tf32.f32 "
        "{%0,%1,%2,%3}, {%4,%5,%6,%7}, {%8,%9}, {%0,%1,%2,%3};"
        : "+f"(c[0]), "+f"(c[1]), "+f"(c[2]), "+f"(c[3])
        : "r"(a[0]), "r"(a[1]), "r"(a[2]), "r"(a[3]), "r"(b0), "r"(b1));
}

__global__ __launch_bounds__(256, 2)
void gemm_tf32_kernel(const float* __restrict__ x,
                      const float* __restrict__ W,
                      const float* __restrict__ aw) {
    __shared__ unsigned Xs[BMT * XPAD];
    __shared__ unsigned Ws[MOUT * XPAD];

    int tid  = threadIdx.x;
    int lane = tid & 31;
    int warp = tid >> 5;
    int g = lane >> 2;
    int t = lane & 3;
    int wm = warp & 3;
    int wn = warp >> 2;
    int row0 = blockIdx.x * BMT;

    float c[2][8][4];
    #pragma unroll
    for (int tm = 0; tm < 2; tm++)
        #pragma unroll
        for (int tn = 0; tn < 8; tn++)
            #pragma unroll
            for (int i = 0; i < 4; i++) c[tm][tn][i] = 0.f;

    for (int k0 = 0; k0 < KIN; k0 += BKT) {
        #pragma unroll
        for (int j = 0; j < 4; j++) {
            int idx = tid + 256 * j;
            int m   = idx >> 3;
            int kv  = (idx & 7) * 4;
            int row = row0 + m;
            float4 v = make_float4(0.f, 0.f, 0.f, 0.f);
            if (row < NN) v = *(const float4*)&x[row * KIN + k0 + kv];
            uint4 u;
            u.x = f2tf32(v.x); u.y = f2tf32(v.y);
            u.z = f2tf32(v.z); u.w = f2tf32(v.w);
            *(uint4*)&Xs[m * XPAD + kv] = u;

            float4 w4 = *(const float4*)&W[m * KIN + k0 + kv];
            uint4 uw;
            uw.x = f2tf32(w4.x); uw.y = f2tf32(w4.y);
            uw.z = f2tf32(w4.z); uw.w = f2tf32(w4.w);
            *(uint4*)&Ws[m * XPAD + kv] = uw;
        }
        __syncthreads();

        #pragma unroll
        for (int kk = 0; kk < BKT; kk += 8) {
            unsigned a[2][4];
            #pragma unroll
            for (int tm = 0; tm < 2; tm++) {
                int r = wm * 32 + tm * 16 + g;
                a[tm][0] = Xs[r * XPAD + kk + t];
                a[tm][1] = Xs[(r + 8) * XPAD + kk + t];
                a[tm][2] = Xs[r * XPAD + kk + t + 4];
                a[tm][3] = Xs[(r + 8) * XPAD + kk + t + 4];
            }
            #pragma unroll
            for (int tn = 0; tn < 8; tn++) {
                int n = wn * 64 + tn * 8 + g;
                unsigned b0 = Ws[n * XPAD + kk + t];
                unsigned b1 = Ws[n * XPAD + kk + t + 4];
                mma_tf32(c[0][tn], a[0], b0, b1);
                mma_tf32(c[1][tn], a[1], b0, b1);
            }
        }
        __syncthreads();
    }

    float as_r[4][2], ad_r[4][2];
    #pragma unroll
    for (int q = 0; q < 4; q++)
        #pragma unroll
        for (int j = 0; j < 2; j++) {
            as_r[q][j] = aw[q * 8 + 2 * t + j];
            ad_r[q][j] = aw[32 + q * 8 + 2 * t + j];
        }

    #pragma unroll
    for (int tm = 0; tm < 2; tm++)
    #pragma unroll
    for (int half = 0; half < 2; half++) {
        int row = row0 + wm * 32 + tm * 16 + half * 8 + g;

        if (row < NN) {
            #pragma unroll
            for (int tn = 0; tn < 8; tn++) {
                __half2 hv = __floats2half2_rn(c[tm][tn][half * 2],
                                               c[tm][tn][half * 2 + 1]);
                *(__half2*)&g_Wx_h[row * MOUT + wn * 64 + tn * 8 + 2 * t] = hv;
            }
        }

        #pragma unroll
        for (int hl = 0; hl < 2; hl++) {
            float ps = 0.f, pd = 0.f;
            #pragma unroll
            for (int q = 0; q < 4; q++)
                #pragma unroll
                for (int j = 0; j < 2; j++) {
                    float v = c[tm][hl * 4 + q][half * 2 + j];
                    ps += v * as_r[q][j];
                    pd += v * ad_r[q][j];
                }
            ps += __shfl_xor_sync(0xffffffffu, ps, 1);
            ps += __shfl_xor_sync(0xffffffffu, ps, 2);
            pd += __shfl_xor_sync(0xffffffffu, pd, 1);
            pd += __shfl_xor_sync(0xffffffffu, pd, 2);
            if (t == 0 && row < NN) {
                g_ssrc[row * NH + wn * 2 + hl] = ps;
                g_sdst[row * NH + wn * 2 + hl] = pd;
            }
        }
    }
}

// ---------------------------------------------------------------------------
// Aggregation: one warp per destination node, fp16 gather, fused ELU.
// (round-4 known-good version)
// ---------------------------------------------------------------------------
__device__ __forceinline__ float lrelu_exp(float v) {
    float r = v > 0.f ? v : 0.2f * v;
    return __expf(r);
}

__global__ __launch_bounds__(256)
void agg_kernel(float* __restrict__ out) {
    int d = blockIdx.x * 8 + (threadIdx.x >> 5);
    if (d >= NN) return;
    int lane = threadIdx.x & 31;
    int beg = g_off[d];
    int end = g_off[d + 1];

    float4 sd4 = *(const float4*)&g_sdst[d * 4];

    // Pass 1: denom
    float4 dn = make_float4(0.f, 0.f, 0.f, 0.f);
    for (int j = beg + lane; j < end; j += 32) {
        int s = g_esrc[j];
        float4 a = *(const float4*)&g_ssrc[s * 4];
        dn.x += lrelu_exp(a.x + sd4.x);
        dn.y += lrelu_exp(a.y + sd4.y);
        dn.z += lrelu_exp(a.z + sd4.z);
        dn.w += lrelu_exp(a.w + sd4.w);
    }
    #pragma unroll
    for (int m = 16; m; m >>= 1) {
        dn.x += __shfl_xor_sync(0xffffffffu, dn.x, m);
        dn.y += __shfl_xor_sync(0xffffffffu, dn.y, m);
        dn.z += __shfl_xor_sync(0xffffffffu, dn.z, m);
        dn.w += __shfl_xor_sync(0xffffffffu, dn.w, m);
    }

    int h = lane >> 3;
    float dnh = (h == 0) ? dn.x : (h == 1) ? dn.y : (h == 2) ? dn.z : dn.w;
    float adh = (h == 0) ? sd4.x : (h == 1) ? sd4.y : (h == 2) ? sd4.z : sd4.w;
    float invd = __fdividef(1.f, dnh + 1e-8f);

    // Pass 2: fp16 weighted gather (8B per lane per edge)
    float4 acc = make_float4(0.f, 0.f, 0.f, 0.f);
    #pragma unroll 2
    for (int j = beg; j < end; j++) {
        int s = g_esrc[j];                               // warp-uniform
        float al = lrelu_exp(g_ssrc[s * 4 + h] + adh) * invd;
        float2 raw = *(const float2*)&g_Wx_h[s * MOUT + lane * 4];
        __half2 h01 = ((__half2*)&raw)[0];
        __half2 h23 = ((__half2*)&raw)[1];
        float2 f01 = __half22float2(h01);
        float2 f23 = __half22float2(h23);
        acc.x += al * f01.x; acc.y += al * f01.y;
        acc.z += al * f23.x; acc.w += al * f23.y;
    }

    acc.x = acc.x > 0.f ? acc.x : expm1f(acc.x);
    acc.y = acc.y > 0.f ? acc.y : expm1f(acc.y);
    acc.z = acc.z > 0.f ? acc.z : expm1f(acc.z);
    acc.w = acc.w > 0.f ? acc.w : expm1f(acc.w);
    *(float4*)&out[d * MOUT + lane * 4] = acc;
}

// ---------------------------------------------------------------------------
// Single-stream, 6 launches (round-4 topology + consolidated scan).
// ---------------------------------------------------------------------------
extern "C" void kernel_launch(void* const* d_in, const int* in_sizes, int n_in,
                              void* d_out, int out_size) {
    const float* x  = (const float*)d_in[0];
    const int*   ei = (const int*)d_in[1];
    const float* W  = (const float*)d_in[2];
    const float* aw = (const float*)d_in[3];
    float* out = (float*)d_out;

    zero2_kernel<<<(NN + 1023) / 1024, 1024>>>();
    gemm_tf32_kernel<<<(NN + BMT - 1) / BMT, 256>>>(x, W, aw);
    hist_kernel<<<(NE + 255) / 256, 256>>>(ei);
    scan_kernel<<<1, 1024>>>();
    fill_kernel<<<(NE / 2 + 255) / 256, 256>>>(ei);
    agg_kernel<<<(NN + 7) / 8, 256>>>(out);
}

// round 7
// speedup vs baseline: 1.3230x; 1.2924x over previous
#include <cuda_runtime.h>
#include <cuda_fp16.h>

#define NN   50000
#define NE   800000
#define KIN  256
#define MOUT 128
#define NH   4
#define NB   196        // ceil(NN/256)

// Scratch (allocation-free rule: __device__ globals)
__device__ __align__(16) __half g_Wx_h[NN * MOUT];  // 12.8 MB fp16 Wx for agg
__device__ __align__(16) float g_ssrc[NN * NH];
__device__ __align__(16) float g_sdst[NN * NH];
__device__ int g_cnt[NN];
__device__ int g_scan[NN];
__device__ int g_bsum[NB];
__device__ int g_off[NN + 1];
__device__ int g_cur[NN];
__device__ int g_esrc[NE];

// ---------------------------------------------------------------------------
// CSR build: zero -> hist -> scan1 (per-block) -> scan_apply -> fill
// ---------------------------------------------------------------------------
__global__ void zero2_kernel() {
    int i = blockIdx.x * blockDim.x + threadIdx.x;
    if (i < NN) { g_cnt[i] = 0; g_cur[i] = 0; }
}

__global__ void hist_kernel(const int* __restrict__ ei) {
    int e = blockIdx.x * blockDim.x + threadIdx.x;
    if (e < NE) atomicAdd(&g_cnt[ei[NE + e]], 1);
}

// Per-block inclusive scan (coalesced, 196 blocks) + block sums
__global__ void scan1_kernel() {
    __shared__ int sh[256];
    int t = threadIdx.x;
    int i = blockIdx.x * 256 + t;
    int v = (i < NN) ? g_cnt[i] : 0;
    sh[t] = v;
    __syncthreads();
    #pragma unroll
    for (int ofs = 1; ofs < 256; ofs <<= 1) {
        int add = (t >= ofs) ? sh[t - ofs] : 0;
        __syncthreads();
        sh[t] += add;
        __syncthreads();
    }
    if (i < NN) g_scan[i] = sh[t];
    if (t == 255) g_bsum[blockIdx.x] = sh[255];
}

// Every block redundantly scans the 196 block sums (L2-hot) and applies.
__global__ void scan_apply_kernel() {
    __shared__ int sh[256];
    int t = threadIdx.x;
    sh[t] = (t < NB) ? g_bsum[t] : 0;
    __syncthreads();
    #pragma unroll
    for (int ofs = 1; ofs < 256; ofs <<= 1) {
        int add = (t >= ofs) ? sh[t - ofs] : 0;
        __syncthreads();
        sh[t] += add;
        __syncthreads();
    }
    int base = (blockIdx.x == 0) ? 0 : sh[blockIdx.x - 1];
    int i = blockIdx.x * 256 + t;
    if (i < NN) g_off[i] = g_scan[i] - g_cnt[i] + base;
    if (i == 0) g_off[NN] = NE;
}

// 2 edges per thread for MLP on the off-load -> atomic -> store chain
__global__ void fill_kernel(const int* __restrict__ ei) {
    int b = (blockIdx.x * blockDim.x + threadIdx.x) * 2;
    if (b >= NE) return;
    int s0 = ei[b];
    int d0 = ei[NE + b];
    int p0 = g_off[d0] + atomicAdd(&g_cur[d0], 1);
    if (b + 1 < NE) {
        int s1 = ei[b + 1];
        int d1 = ei[NE + b + 1];
        int p1 = g_off[d1] + atomicAdd(&g_cur[d1], 1);
        g_esrc[p1] = s1;
    }
    g_esrc[p0] = s0;
}

// ---------------------------------------------------------------------------
// tf32 tensor-core GEMM: Wx = x @ W^T, 128x128 block tile, 8 warps (4x2),
// warp = 32x64 = 2x8 m16n8k8 tiles. Fused fp16 Wx store + per-head scores.
// ---------------------------------------------------------------------------
#define BMT 128
#define BKT 32
#define XPAD 36

__device__ __forceinline__ unsigned f2tf32(float f) {
    unsigned u;
    asm("cvt.rna.tf32.f32 %0, %1;" : "=r"(u) : "f"(f));
    return u;
}

__device__ __forceinline__ void mma_tf32(float* c, const unsigned* a,
                                         unsigned b0, unsigned b1) {
    asm volatile(
        "mma.sync.aligned.m16n8k8.row.col.f32.tf32.tf32.f32 "
        "{%0,%1,%2,%3}, {%4,%5,%6,%7}, {%8,%9}, {%0,%1,%2,%3};"
        : "+f"(c[0]), "+f"(c[1]), "+f"(c[2]), "+f"(c[3])
        : "r"(a[0]), "r"(a[1]), "r"(a[2]), "r"(a[3]), "r"(b0), "r"(b1));
}

__global__ __launch_bounds__(256, 2)
void gemm_tf32_kernel(const float* __restrict__ x,
                      const float* __restrict__ W,
                      const float* __restrict__ aw) {
    __shared__ unsigned Xs[BMT * XPAD];
    __shared__ unsigned Ws[MOUT * XPAD];

    int tid  = threadIdx.x;
    int lane = tid & 31;
    int warp = tid >> 5;
    int g = lane >> 2;
    int t = lane & 3;
    int wm = warp & 3;
    int wn = warp >> 2;
    int row0 = blockIdx.x * BMT;

    float c[2][8][4];
    #pragma unroll
    for (int tm = 0; tm < 2; tm++)
        #pragma unroll
        for (int tn = 0; tn < 8; tn++)
            #pragma unroll
            for (int i = 0; i < 4; i++) c[tm][tn][i] = 0.f;

    for (int k0 = 0; k0 < KIN; k0 += BKT) {
        #pragma unroll
        for (int j = 0; j < 4; j++) {
            int idx = tid + 256 * j;
            int m   = idx >> 3;
            int kv  = (idx & 7) * 4;
            int row = row0 + m;
            float4 v = make_float4(0.f, 0.f, 0.f, 0.f);
            if (row < NN) v = *(const float4*)&x[row * KIN + k0 + kv];
            uint4 u;
            u.x = f2tf32(v.x); u.y = f2tf32(v.y);
            u.z = f2tf32(v.z); u.w = f2tf32(v.w);
            *(uint4*)&Xs[m * XPAD + kv] = u;

            float4 w4 = *(const float4*)&W[m * KIN + k0 + kv];
            uint4 uw;
            uw.x = f2tf32(w4.x); uw.y = f2tf32(w4.y);
            uw.z = f2tf32(w4.z); uw.w = f2tf32(w4.w);
            *(uint4*)&Ws[m * XPAD + kv] = uw;
        }
        __syncthreads();

        #pragma unroll
        for (int kk = 0; kk < BKT; kk += 8) {
            unsigned a[2][4];
            #pragma unroll
            for (int tm = 0; tm < 2; tm++) {
                int r = wm * 32 + tm * 16 + g;
                a[tm][0] = Xs[r * XPAD + kk + t];
                a[tm][1] = Xs[(r + 8) * XPAD + kk + t];
                a[tm][2] = Xs[r * XPAD + kk + t + 4];
                a[tm][3] = Xs[(r + 8) * XPAD + kk + t + 4];
            }
            #pragma unroll
            for (int tn = 0; tn < 8; tn++) {
                int n = wn * 64 + tn * 8 + g;
                unsigned b0 = Ws[n * XPAD + kk + t];
                unsigned b1 = Ws[n * XPAD + kk + t + 4];
                mma_tf32(c[0][tn], a[0], b0, b1);
                mma_tf32(c[1][tn], a[1], b0, b1);
            }
        }
        __syncthreads();
    }

    float as_r[4][2], ad_r[4][2];
    #pragma unroll
    for (int q = 0; q < 4; q++)
        #pragma unroll
        for (int j = 0; j < 2; j++) {
            as_r[q][j] = aw[q * 8 + 2 * t + j];
            ad_r[q][j] = aw[32 + q * 8 + 2 * t + j];
        }

    #pragma unroll
    for (int tm = 0; tm < 2; tm++)
    #pragma unroll
    for (int half = 0; half < 2; half++) {
        int row = row0 + wm * 32 + tm * 16 + half * 8 + g;

        if (row < NN) {
            #pragma unroll
            for (int tn = 0; tn < 8; tn++) {
                __half2 hv = __floats2half2_rn(c[tm][tn][half * 2],
                                               c[tm][tn][half * 2 + 1]);
                *(__half2*)&g_Wx_h[row * MOUT + wn * 64 + tn * 8 + 2 * t] = hv;
            }
        }

        #pragma unroll
        for (int hl = 0; hl < 2; hl++) {
            float ps = 0.f, pd = 0.f;
            #pragma unroll
            for (int q = 0; q < 4; q++)
                #pragma unroll
                for (int j = 0; j < 2; j++) {
                    float v = c[tm][hl * 4 + q][half * 2 + j];
                    ps += v * as_r[q][j];
                    pd += v * ad_r[q][j];
                }
            ps += __shfl_xor_sync(0xffffffffu, ps, 1);
            ps += __shfl_xor_sync(0xffffffffu, ps, 2);
            pd += __shfl_xor_sync(0xffffffffu, pd, 1);
            pd += __shfl_xor_sync(0xffffffffu, pd, 2);
            if (t == 0 && row < NN) {
                g_ssrc[row * NH + wn * 2 + hl] = ps;
                g_sdst[row * NH + wn * 2 + hl] = pd;
            }
        }
    }
}

// ---------------------------------------------------------------------------
// Aggregation: warp per dst node, smem numerator cache, fp16 gather, ELU.
// ---------------------------------------------------------------------------
#define CAP 64

__device__ __forceinline__ float lrelu_exp(float v) {
    float r = v > 0.f ? v : 0.2f * v;
    return __expf(r);
}

__global__ __launch_bounds__(256)
void agg_kernel(float* __restrict__ out) {
    __shared__ float s_al[8][CAP][4];   // 8 KB: per-warp edge numerators

    int w = threadIdx.x >> 5;
    int d = blockIdx.x * 8 + w;
    if (d >= NN) return;
    int lane = threadIdx.x & 31;
    int beg = g_off[d];
    int end = g_off[d + 1];
    int deg = end - beg;

    float4 sd4 = *(const float4*)&g_sdst[d * 4];

    // Pass 1: numerators -> smem cache + denom reduction
    float4 dn = make_float4(0.f, 0.f, 0.f, 0.f);
    for (int j = lane; j < deg; j += 32) {
        int s = g_esrc[beg + j];
        float4 a = *(const float4*)&g_ssrc[s * 4];
        float4 e;
        e.x = lrelu_exp(a.x + sd4.x);
        e.y = lrelu_exp(a.y + sd4.y);
        e.z = lrelu_exp(a.z + sd4.z);
        e.w = lrelu_exp(a.w + sd4.w);
        dn.x += e.x; dn.y += e.y; dn.z += e.z; dn.w += e.w;
        if (j < CAP) *(float4*)&s_al[w][j][0] = e;
    }
    #pragma unroll
    for (int m = 16; m; m >>= 1) {
        dn.x += __shfl_xor_sync(0xffffffffu, dn.x, m);
        dn.y += __shfl_xor_sync(0xffffffffu, dn.y, m);
        dn.z += __shfl_xor_sync(0xffffffffu, dn.z, m);
        dn.w += __shfl_xor_sync(0xffffffffu, dn.w, m);
    }
    __syncwarp();

    int h = lane >> 3;
    float dnh = (h == 0) ? dn.x : (h == 1) ? dn.y : (h == 2) ? dn.z : dn.w;
    float adh = (h == 0) ? sd4.x : (h == 1) ? sd4.y : (h == 2) ? sd4.z : sd4.w;
    float invd = __fdividef(1.f, dnh + 1e-8f);

    // Pass 2: fp16 weighted gather (8B per lane per edge)
    float4 acc = make_float4(0.f, 0.f, 0.f, 0.f);
    #pragma unroll 4
    for (int j = 0; j < deg; j++) {
        int s = g_esrc[beg + j];                         // warp-uniform, L1-hot
        float al;
        if (j < CAP) al = s_al[w][j][h] * invd;
        else         al = lrelu_exp(g_ssrc[s * 4 + h] + adh) * invd;
        float2 raw = *(const float2*)&g_Wx_h[s * MOUT + lane * 4];
        __half2 h01 = ((__half2*)&raw)[0];
        __half2 h23 = ((__half2*)&raw)[1];
        float2 f01 = __half22float2(h01);
        float2 f23 = __half22float2(h23);
        acc.x += al * f01.x; acc.y += al * f01.y;
        acc.z += al * f23.x; acc.w += al * f23.y;
    }

    acc.x = acc.x > 0.f ? acc.x : expm1f(acc.x);
    acc.y = acc.y > 0.f ? acc.y : expm1f(acc.y);
    acc.z = acc.z > 0.f ? acc.z : expm1f(acc.z);
    acc.w = acc.w > 0.f ? acc.w : expm1f(acc.w);
    *(float4*)&out[d * MOUT + lane * 4] = acc;
}

// ---------------------------------------------------------------------------
extern "C" void kernel_launch(void* const* d_in, const int* in_sizes, int n_in,
                              void* d_out, int out_size) {
    const float* x  = (const float*)d_in[0];
    const int*   ei = (const int*)d_in[1];
    const float* W  = (const float*)d_in[2];
    const float* aw = (const float*)d_in[3];
    float* out = (float*)d_out;

    zero2_kernel<<<(NN + 1023) / 1024, 1024>>>();
    gemm_tf32_kernel<<<(NN + BMT - 1) / BMT, 256>>>(x, W, aw);
    hist_kernel<<<(NE + 255) / 256, 256>>>(ei);
    scan1_kernel<<<NB, 256>>>();
    scan_apply_kernel<<<NB, 256>>>();
    fill_kernel<<<(NE / 2 + 255) / 256, 256>>>(ei);
    agg_kernel<<<(NN + 7) / 8, 256>>>(out);
}

// round 8
// speedup vs baseline: 1.3700x; 1.0356x over previous
#include <cuda_runtime.h>
#include <cuda_fp16.h>

#define NN   50000
#define NE   800000
#define KIN  256
#define MOUT 128
#define NH   4
#define NB   196        // ceil(NN/256)

// Scratch (allocation-free rule: __device__ globals)
__device__ __align__(16) __half g_Wx_h[NN * MOUT];  // 12.8 MB fp16 Wx for agg
__device__ __align__(16) float g_ssrc[NN * NH];
__device__ __align__(16) float g_sdst[NN * NH];
__device__ int g_cnt[NN];
__device__ int g_scan[NN];
__device__ int g_bsum[NB];
__device__ int g_off[NN + 1];
__device__ int g_cur[NN];
__device__ int g_esrc[NE];

// ---------------------------------------------------------------------------
// CSR build: zero -> hist -> scan1 (per-block) -> scan_apply -> fill
// ---------------------------------------------------------------------------
__global__ void zero2_kernel() {
    int i = blockIdx.x * blockDim.x + threadIdx.x;
    if (i < NN) { g_cnt[i] = 0; g_cur[i] = 0; }
}

__global__ void hist_kernel(const int* __restrict__ ei) {
    int e = blockIdx.x * blockDim.x + threadIdx.x;
    if (e < NE) atomicAdd(&g_cnt[ei[NE + e]], 1);
}

// Per-block inclusive scan (coalesced, 196 blocks) + block sums
__global__ void scan1_kernel() {
    __shared__ int sh[256];
    int t = threadIdx.x;
    int i = blockIdx.x * 256 + t;
    int v = (i < NN) ? g_cnt[i] : 0;
    sh[t] = v;
    __syncthreads();
    #pragma unroll
    for (int ofs = 1; ofs < 256; ofs <<= 1) {
        int add = (t >= ofs) ? sh[t - ofs] : 0;
        __syncthreads();
        sh[t] += add;
        __syncthreads();
    }
    if (i < NN) g_scan[i] = sh[t];
    if (t == 255) g_bsum[blockIdx.x] = sh[255];
}

// Every block redundantly scans the 196 block sums (L2-hot) and applies.
__global__ void scan_apply_kernel() {
    __shared__ int sh[256];
    int t = threadIdx.x;
    sh[t] = (t < NB) ? g_bsum[t] : 0;
    __syncthreads();
    #pragma unroll
    for (int ofs = 1; ofs < 256; ofs <<= 1) {
        int add = (t >= ofs) ? sh[t - ofs] : 0;
        __syncthreads();
        sh[t] += add;
        __syncthreads();
    }
    int base = (blockIdx.x == 0) ? 0 : sh[blockIdx.x - 1];
    int i = blockIdx.x * 256 + t;
    if (i < NN) g_off[i] = g_scan[i] - g_cnt[i] + base;
    if (i == 0) g_off[NN] = NE;
}

// 4 edges per thread for MLP on the off-load -> atomic -> store chain
__global__ void fill_kernel(const int* __restrict__ ei) {
    int b = (blockIdx.x * blockDim.x + threadIdx.x) * 4;
    if (b >= NE) return;
    int n = (NE - b < 4) ? (NE - b) : 4;
    int s[4], d[4], p[4];
    #pragma unroll
    for (int j = 0; j < 4; j++) {
        if (j < n) {
            s[j] = ei[b + j];
            d[j] = ei[NE + b + j];
        }
    }
    #pragma unroll
    for (int j = 0; j < 4; j++)
        if (j < n) p[j] = g_off[d[j]] + atomicAdd(&g_cur[d[j]], 1);
    #pragma unroll
    for (int j = 0; j < 4; j++)
        if (j < n) g_esrc[p[j]] = s[j];
}

// ---------------------------------------------------------------------------
// tf32 tensor-core GEMM: Wx = x @ W^T, 128x128 block tile, 8 warps (4x2),
// warp = 32x64 = 2x8 m16n8k8 tiles. Fused fp16 Wx store + per-head scores.
// ---------------------------------------------------------------------------
#define BMT 128
#define BKT 32
#define XPAD 36

__device__ __forceinline__ unsigned f2tf32(float f) {
    unsigned u;
    asm("cvt.rna.tf32.f32 %0, %1;" : "=r"(u) : "f"(f));
    return u;
}

__device__ __forceinline__ void mma_tf32(float* c, const unsigned* a,
                                         unsigned b0, unsigned b1) {
    asm volatile(
        "mma.sync.aligned.m16n8k8.row.col.f32.tf32.tf32.f32 "
        "{%0,%1,%2,%3}, {%4,%5,%6,%7}, {%8,%9}, {%0,%1,%2,%3};"
        : "+f"(c[0]), "+f"(c[1]), "+f"(c[2]), "+f"(c[3])
        : "r"(a[0]), "r"(a[1]), "r"(a[2]), "r"(a[3]), "r"(b0), "r"(b1));
}

__global__ __launch_bounds__(256, 2)
void gemm_tf32_kernel(const float* __restrict__ x,
                      const float* __restrict__ W,
                      const float* __restrict__ aw) {
    __shared__ unsigned Xs[BMT * XPAD];
    __shared__ unsigned Ws[MOUT * XPAD];

    int tid  = threadIdx.x;
    int lane = tid & 31;
    int warp = tid >> 5;
    int g = lane >> 2;
    int t = lane & 3;
    int wm = warp & 3;
    int wn = warp >> 2;
    int row0 = blockIdx.x * BMT;

    float c[2][8][4];
    #pragma unroll
    for (int tm = 0; tm < 2; tm++)
        #pragma unroll
        for (int tn = 0; tn < 8; tn++)
            #pragma unroll
            for (int i = 0; i < 4; i++) c[tm][tn][i] = 0.f;

    for (int k0 = 0; k0 < KIN; k0 += BKT) {
        #pragma unroll
        for (int j = 0; j < 4; j++) {
            int idx = tid + 256 * j;
            int m   = idx >> 3;
            int kv  = (idx & 7) * 4;
            int row = row0 + m;
            float4 v = make_float4(0.f, 0.f, 0.f, 0.f);
            if (row < NN) v = *(const float4*)&x[row * KIN + k0 + kv];
            uint4 u;
            u.x = f2tf32(v.x); u.y = f2tf32(v.y);
            u.z = f2tf32(v.z); u.w = f2tf32(v.w);
            *(uint4*)&Xs[m * XPAD + kv] = u;

            float4 w4 = *(const float4*)&W[m * KIN + k0 + kv];
            uint4 uw;
            uw.x = f2tf32(w4.x); uw.y = f2tf32(w4.y);
            uw.z = f2tf32(w4.z); uw.w = f2tf32(w4.w);
            *(uint4*)&Ws[m * XPAD + kv] = uw;
        }
        __syncthreads();

        #pragma unroll
        for (int kk = 0; kk < BKT; kk += 8) {
            unsigned a[2][4];
            #pragma unroll
            for (int tm = 0; tm < 2; tm++) {
                int r = wm * 32 + tm * 16 + g;
                a[tm][0] = Xs[r * XPAD + kk + t];
                a[tm][1] = Xs[(r + 8) * XPAD + kk + t];
                a[tm][2] = Xs[r * XPAD + kk + t + 4];
                a[tm][3] = Xs[(r + 8) * XPAD + kk + t + 4];
            }
            #pragma unroll
            for (int tn = 0; tn < 8; tn++) {
                int n = wn * 64 + tn * 8 + g;
                unsigned b0 = Ws[n * XPAD + kk + t];
                unsigned b1 = Ws[n * XPAD + kk + t + 4];
                mma_tf32(c[0][tn], a[0], b0, b1);
                mma_tf32(c[1][tn], a[1], b0, b1);
            }
        }
        __syncthreads();
    }

    float as_r[4][2], ad_r[4][2];
    #pragma unroll
    for (int q = 0; q < 4; q++)
        #pragma unroll
        for (int j = 0; j < 2; j++) {
            as_r[q][j] = aw[q * 8 + 2 * t + j];
            ad_r[q][j] = aw[32 + q * 8 + 2 * t + j];
        }

    #pragma unroll
    for (int tm = 0; tm < 2; tm++)
    #pragma unroll
    for (int half = 0; half < 2; half++) {
        int row = row0 + wm * 32 + tm * 16 + half * 8 + g;

        if (row < NN) {
            #pragma unroll
            for (int tn = 0; tn < 8; tn++) {
                __half2 hv = __floats2half2_rn(c[tm][tn][half * 2],
                                               c[tm][tn][half * 2 + 1]);
                *(__half2*)&g_Wx_h[row * MOUT + wn * 64 + tn * 8 + 2 * t] = hv;
            }
        }

        #pragma unroll
        for (int hl = 0; hl < 2; hl++) {
            float ps = 0.f, pd = 0.f;
            #pragma unroll
            for (int q = 0; q < 4; q++)
                #pragma unroll
                for (int j = 0; j < 2; j++) {
                    float v = c[tm][hl * 4 + q][half * 2 + j];
                    ps += v * as_r[q][j];
                    pd += v * ad_r[q][j];
                }
            ps += __shfl_xor_sync(0xffffffffu, ps, 1);
            ps += __shfl_xor_sync(0xffffffffu, ps, 2);
            pd += __shfl_xor_sync(0xffffffffu, pd, 1);
            pd += __shfl_xor_sync(0xffffffffu, pd, 2);
            if (t == 0 && row < NN) {
                g_ssrc[row * NH + wn * 2 + hl] = ps;
                g_sdst[row * NH + wn * 2 + hl] = pd;
            }
        }
    }
}

// ---------------------------------------------------------------------------
// Aggregation: one warp per destination node, fp16 gather, fused ELU.
// (round-4 known-good version — plain pass 2, no smem cache)
// ---------------------------------------------------------------------------
__device__ __forceinline__ float lrelu_exp(float v) {
    float r = v > 0.f ? v : 0.2f * v;
    return __expf(r);
}

__global__ __launch_bounds__(256)
void agg_kernel(float* __restrict__ out) {
    int d = blockIdx.x * 8 + (threadIdx.x >> 5);
    if (d >= NN) return;
    int lane = threadIdx.x & 31;
    int beg = g_off[d];
    int end = g_off[d + 1];

    float4 sd4 = *(const float4*)&g_sdst[d * 4];

    // Pass 1: denom
    float4 dn = make_float4(0.f, 0.f, 0.f, 0.f);
    for (int j = beg + lane; j < end; j += 32) {
        int s = g_esrc[j];
        float4 a = *(const float4*)&g_ssrc[s * 4];
        dn.x += lrelu_exp(a.x + sd4.x);
        dn.y += lrelu_exp(a.y + sd4.y);
        dn.z += lrelu_exp(a.z + sd4.z);
        dn.w += lrelu_exp(a.w + sd4.w);
    }
    #pragma unroll
    for (int m = 16; m; m >>= 1) {
        dn.x += __shfl_xor_sync(0xffffffffu, dn.x, m);
        dn.y += __shfl_xor_sync(0xffffffffu, dn.y, m);
        dn.z += __shfl_xor_sync(0xffffffffu, dn.z, m);
        dn.w += __shfl_xor_sync(0xffffffffu, dn.w, m);
    }

    int h = lane >> 3;
    float dnh = (h == 0) ? dn.x : (h == 1) ? dn.y : (h == 2) ? dn.z : dn.w;
    float adh = (h == 0) ? sd4.x : (h == 1) ? sd4.y : (h == 2) ? sd4.z : sd4.w;
    float invd = __fdividef(1.f, dnh + 1e-8f);

    // Pass 2: fp16 weighted gather (8B per lane per edge)
    float4 acc = make_float4(0.f, 0.f, 0.f, 0.f);
    #pragma unroll 2
    for (int j = beg; j < end; j++) {
        int s = g_esrc[j];                               // warp-uniform
        float al = lrelu_exp(g_ssrc[s * 4 + h] + adh) * invd;
        float2 raw = *(const float2*)&g_Wx_h[s * MOUT + lane * 4];
        __half2 h01 = ((__half2*)&raw)[0];
        __half2 h23 = ((__half2*)&raw)[1];
        float2 f01 = __half22float2(h01);
        float2 f23 = __half22float2(h23);
        acc.x += al * f01.x; acc.y += al * f01.y;
        acc.z += al * f23.x; acc.w += al * f23.y;
    }

    acc.x = acc.x > 0.f ? acc.x : expm1f(acc.x);
    acc.y = acc.y > 0.f ? acc.y : expm1f(acc.y);
    acc.z = acc.z > 0.f ? acc.z : expm1f(acc.z);
    acc.w = acc.w > 0.f ? acc.w : expm1f(acc.w);
    *(float4*)&out[d * MOUT + lane * 4] = acc;
}

// ---------------------------------------------------------------------------
extern "C" void kernel_launch(void* const* d_in, const int* in_sizes, int n_in,
                              void* d_out, int out_size) {
    const float* x  = (const float*)d_in[0];
    const int*   ei = (const int*)d_in[1];
    const float* W  = (const float*)d_in[2];
    const float* aw = (const float*)d_in[3];
    float* out = (float*)d_out;

    zero2_kernel<<<(NN + 1023) / 1024, 1024>>>();
    gemm_tf32_kernel<<<(NN + BMT - 1) / BMT, 256>>>(x, W, aw);
    hist_kernel<<<(NE + 255) / 256, 256>>>(ei);
    scan1_kernel<<<NB, 256>>>();
    scan_apply_kernel<<<NB, 256>>>();
    fill_kernel<<<(NE / 4 + 255) / 256, 256>>>(ei);
    agg_kernel<<<(NN + 7) / 8, 256>>>(out);
}

// round 9
// speedup vs baseline: 1.4527x; 1.0604x over previous
#include <cuda_runtime.h>
#include <cuda_fp16.h>

#define NN   50000
#define NE   800000
#define KIN  256
#define MOUT 128
#define NH   4
#define NB   196        // ceil(NN/256)

// Scratch (allocation-free rule: __device__ globals)
__device__ __align__(16) __half g_Wx_h[NN * MOUT];  // 12.8 MB fp16 Wx for agg
__device__ __align__(16) float g_ssrc[NN * NH];
__device__ __align__(16) float g_sdst[NN * NH];
__device__ int g_cnt[NN];
__device__ int g_scan[NN];
__device__ int g_bsum[NB];
__device__ int g_off[NN + 1];
__device__ int g_cur[NN];
__device__ int g_esrc[NE];

// ---------------------------------------------------------------------------
// CSR build: zero -> hist -> scan1 (per-block) -> scan_apply -> fill
// ---------------------------------------------------------------------------
__global__ void zero2_kernel() {
    int i = blockIdx.x * blockDim.x + threadIdx.x;
    if (i < NN) { g_cnt[i] = 0; g_cur[i] = 0; }
}

__global__ void hist_kernel(const int* __restrict__ ei) {
    int e = blockIdx.x * blockDim.x + threadIdx.x;
    if (e < NE) atomicAdd(&g_cnt[ei[NE + e]], 1);
}

// Per-block inclusive scan (coalesced, 196 blocks) + block sums
__global__ void scan1_kernel() {
    __shared__ int sh[256];
    int t = threadIdx.x;
    int i = blockIdx.x * 256 + t;
    int v = (i < NN) ? g_cnt[i] : 0;
    sh[t] = v;
    __syncthreads();
    #pragma unroll
    for (int ofs = 1; ofs < 256; ofs <<= 1) {
        int add = (t >= ofs) ? sh[t - ofs] : 0;
        __syncthreads();
        sh[t] += add;
        __syncthreads();
    }
    if (i < NN) g_scan[i] = sh[t];
    if (t == 255) g_bsum[blockIdx.x] = sh[255];
}

// Every block redundantly scans the 196 block sums (L2-hot) and applies.
__global__ void scan_apply_kernel() {
    __shared__ int sh[256];
    int t = threadIdx.x;
    sh[t] = (t < NB) ? g_bsum[t] : 0;
    __syncthreads();
    #pragma unroll
    for (int ofs = 1; ofs < 256; ofs <<= 1) {
        int add = (t >= ofs) ? sh[t - ofs] : 0;
        __syncthreads();
        sh[t] += add;
        __syncthreads();
    }
    int base = (blockIdx.x == 0) ? 0 : sh[blockIdx.x - 1];
    int i = blockIdx.x * 256 + t;
    if (i < NN) g_off[i] = g_scan[i] - g_cnt[i] + base;
    if (i == 0) g_off[NN] = NE;
}

// 4 edges per thread for MLP on the off-load -> atomic -> store chain
__global__ void fill_kernel(const int* __restrict__ ei) {
    int b = (blockIdx.x * blockDim.x + threadIdx.x) * 4;
    if (b >= NE) return;
    int n = (NE - b < 4) ? (NE - b) : 4;
    int s[4], d[4], p[4];
    #pragma unroll
    for (int j = 0; j < 4; j++) {
        if (j < n) {
            s[j] = ei[b + j];
            d[j] = ei[NE + b + j];
        }
    }
    #pragma unroll
    for (int j = 0; j < 4; j++)
        if (j < n) p[j] = g_off[d[j]] + atomicAdd(&g_cur[d[j]], 1);
    #pragma unroll
    for (int j = 0; j < 4; j++)
        if (j < n) g_esrc[p[j]] = s[j];
}

// ---------------------------------------------------------------------------
// tf32 tensor-core GEMM: Wx = x @ W^T, 128x128 block tile, 8 warps (4x2),
// warp = 32x64 = 2x8 m16n8k8 tiles. Fused fp16 Wx store + per-head scores.
// ---------------------------------------------------------------------------
#define BMT 128
#define BKT 32
#define XPAD 36

__device__ __forceinline__ unsigned f2tf32(float f) {
    unsigned u;
    asm("cvt.rna.tf32.f32 %0, %1;" : "=r"(u) : "f"(f));
    return u;
}

__device__ __forceinline__ void mma_tf32(float* c, const unsigned* a,
                                         unsigned b0, unsigned b1) {
    asm volatile(
        "mma.sync.aligned.m16n8k8.row.col.f32.tf32.tf32.f32 "
        "{%0,%1,%2,%3}, {%4,%5,%6,%7}, {%8,%9}, {%0,%1,%2,%3};"
        : "+f"(c[0]), "+f"(c[1]), "+f"(c[2]), "+f"(c[3])
        : "r"(a[0]), "r"(a[1]), "r"(a[2]), "r"(a[3]), "r"(b0), "r"(b1));
}

__global__ __launch_bounds__(256, 2)
void gemm_tf32_kernel(const float* __restrict__ x,
                      const float* __restrict__ W,
                      const float* __restrict__ aw) {
    __shared__ unsigned Xs[BMT * XPAD];
    __shared__ unsigned Ws[MOUT * XPAD];

    int tid  = threadIdx.x;
    int lane = tid & 31;
    int warp = tid >> 5;
    int g = lane >> 2;
    int t = lane & 3;
    int wm = warp & 3;
    int wn = warp >> 2;
    int row0 = blockIdx.x * BMT;

    float c[2][8][4];
    #pragma unroll
    for (int tm = 0; tm < 2; tm++)
        #pragma unroll
        for (int tn = 0; tn < 8; tn++)
            #pragma unroll
            for (int i = 0; i < 4; i++) c[tm][tn][i] = 0.f;

    for (int k0 = 0; k0 < KIN; k0 += BKT) {
        #pragma unroll
        for (int j = 0; j < 4; j++) {
            int idx = tid + 256 * j;
            int m   = idx >> 3;
            int kv  = (idx & 7) * 4;
            int row = row0 + m;
            float4 v = make_float4(0.f, 0.f, 0.f, 0.f);
            if (row < NN) v = *(const float4*)&x[row * KIN + k0 + kv];
            uint4 u;
            u.x = f2tf32(v.x); u.y = f2tf32(v.y);
            u.z = f2tf32(v.z); u.w = f2tf32(v.w);
            *(uint4*)&Xs[m * XPAD + kv] = u;

            float4 w4 = *(const float4*)&W[m * KIN + k0 + kv];
            uint4 uw;
            uw.x = f2tf32(w4.x); uw.y = f2tf32(w4.y);
            uw.z = f2tf32(w4.z); uw.w = f2tf32(w4.w);
            *(uint4*)&Ws[m * XPAD + kv] = uw;
        }
        __syncthreads();

        #pragma unroll
        for (int kk = 0; kk < BKT; kk += 8) {
            unsigned a[2][4];
            #pragma unroll
            for (int tm = 0; tm < 2; tm++) {
                int r = wm * 32 + tm * 16 + g;
                a[tm][0] = Xs[r * XPAD + kk + t];
                a[tm][1] = Xs[(r + 8) * XPAD + kk + t];
                a[tm][2] = Xs[r * XPAD + kk + t + 4];
                a[tm][3] = Xs[(r + 8) * XPAD + kk + t + 4];
            }
            #pragma unroll
            for (int tn = 0; tn < 8; tn++) {
                int n = wn * 64 + tn * 8 + g;
                unsigned b0 = Ws[n * XPAD + kk + t];
                unsigned b1 = Ws[n * XPAD + kk + t + 4];
                mma_tf32(c[0][tn], a[0], b0, b1);
                mma_tf32(c[1][tn], a[1], b0, b1);
            }
        }
        __syncthreads();
    }

    float as_r[4][2], ad_r[4][2];
    #pragma unroll
    for (int q = 0; q < 4; q++)
        #pragma unroll
        for (int j = 0; j < 2; j++) {
            as_r[q][j] = aw[q * 8 + 2 * t + j];
            ad_r[q][j] = aw[32 + q * 8 + 2 * t + j];
        }

    #pragma unroll
    for (int tm = 0; tm < 2; tm++)
    #pragma unroll
    for (int half = 0; half < 2; half++) {
        int row = row0 + wm * 32 + tm * 16 + half * 8 + g;

        if (row < NN) {
            #pragma unroll
            for (int tn = 0; tn < 8; tn++) {
                __half2 hv = __floats2half2_rn(c[tm][tn][half * 2],
                                               c[tm][tn][half * 2 + 1]);
                *(__half2*)&g_Wx_h[row * MOUT + wn * 64 + tn * 8 + 2 * t] = hv;
            }
        }

        #pragma unroll
        for (int hl = 0; hl < 2; hl++) {
            float ps = 0.f, pd = 0.f;
            #pragma unroll
            for (int q = 0; q < 4; q++)
                #pragma unroll
                for (int j = 0; j < 2; j++) {
                    float v = c[tm][hl * 4 + q][half * 2 + j];
                    ps += v * as_r[q][j];
                    pd += v * ad_r[q][j];
                }
            ps += __shfl_xor_sync(0xffffffffu, ps, 1);
            ps += __shfl_xor_sync(0xffffffffu, ps, 2);
            pd += __shfl_xor_sync(0xffffffffu, pd, 1);
            pd += __shfl_xor_sync(0xffffffffu, pd, 2);
            if (t == 0 && row < NN) {
                g_ssrc[row * NH + wn * 2 + hl] = ps;
                g_sdst[row * NH + wn * 2 + hl] = pd;
            }
        }
    }
}

// ---------------------------------------------------------------------------
// Aggregation: warp per dst node. Pass 1 caches per-edge numerators in smem;
// pass 2 chooses (warp-uniformly!) a branch-free fast loop when deg <= CAP.
// ---------------------------------------------------------------------------
#define CAP 64

__device__ __forceinline__ float lrelu_exp(float v) {
    float r = v > 0.f ? v : 0.2f * v;
    return __expf(r);
}

__global__ __launch_bounds__(256)
void agg_kernel(float* __restrict__ out) {
    __shared__ float s_al[8][CAP][NH];   // 8 KB per block

    int w = threadIdx.x >> 5;
    int d = blockIdx.x * 8 + w;
    if (d >= NN) return;
    int lane = threadIdx.x & 31;
    int beg = g_off[d];
    int deg = g_off[d + 1] - beg;

    float4 sd4 = *(const float4*)&g_sdst[d * 4];

    // Pass 1: per-edge numerators -> smem + denom reduction
    float4 dn = make_float4(0.f, 0.f, 0.f, 0.f);
    for (int j = lane; j < deg; j += 32) {
        int s = g_esrc[beg + j];
        float4 a = *(const float4*)&g_ssrc[s * 4];
        float4 e;
        e.x = lrelu_exp(a.x + sd4.x);
        e.y = lrelu_exp(a.y + sd4.y);
        e.z = lrelu_exp(a.z + sd4.z);
        e.w = lrelu_exp(a.w + sd4.w);
        dn.x += e.x; dn.y += e.y; dn.z += e.z; dn.w += e.w;
        if (j < CAP) *(float4*)&s_al[w][j][0] = e;
    }
    #pragma unroll
    for (int m = 16; m; m >>= 1) {
        dn.x += __shfl_xor_sync(0xffffffffu, dn.x, m);
        dn.y += __shfl_xor_sync(0xffffffffu, dn.y, m);
        dn.z += __shfl_xor_sync(0xffffffffu, dn.z, m);
        dn.w += __shfl_xor_sync(0xffffffffu, dn.w, m);
    }
    __syncwarp();

    int h = lane >> 3;
    float dnh = (h == 0) ? dn.x : (h == 1) ? dn.y : (h == 2) ? dn.z : dn.w;
    float adh = (h == 0) ? sd4.x : (h == 1) ? sd4.y : (h == 2) ? sd4.z : sd4.w;
    float invd = __fdividef(1.f, dnh + 1e-8f);

    // Pass 2: weighted fp16 gather
    float4 acc = make_float4(0.f, 0.f, 0.f, 0.f);
    if (deg <= CAP) {
        // fast loop: alpha from smem (LDS broadcast), no exp, no branch
        const float* al_base = &s_al[w][0][h];
        #pragma unroll 4
        for (int j = 0; j < deg; j++) {
            float al = al_base[j * NH] * invd;
            int s = g_esrc[beg + j];                     // warp-uniform, L1-hot
            float2 raw = *(const float2*)&g_Wx_h[s * MOUT + lane * 4];
            __half2 h01 = ((__half2*)&raw)[0];
            __half2 h23 = ((__half2*)&raw)[1];
            float2 f01 = __half22float2(h01);
            float2 f23 = __half22float2(h23);
            acc.x += al * f01.x; acc.y += al * f01.y;
            acc.z += al * f23.x; acc.w += al * f23.y;
        }
    } else {
        // safe fallback: recompute numerator per edge (R4 path)
        #pragma unroll 2
        for (int j = 0; j < deg; j++) {
            int s = g_esrc[beg + j];
            float al = lrelu_exp(g_ssrc[s * 4 + h] + adh) * invd;
            float2 raw = *(const float2*)&g_Wx_h[s * MOUT + lane * 4];
            __half2 h01 = ((__half2*)&raw)[0];
            __half2 h23 = ((__half2*)&raw)[1];
            float2 f01 = __half22float2(h01);
            float2 f23 = __half22float2(h23);
            acc.x += al * f01.x; acc.y += al * f01.y;
            acc.z += al * f23.x; acc.w += al * f23.y;
        }
    }

    acc.x = acc.x > 0.f ? acc.x : expm1f(acc.x);
    acc.y = acc.y > 0.f ? acc.y : expm1f(acc.y);
    acc.z = acc.z > 0.f ? acc.z : expm1f(acc.z);
    acc.w = acc.w > 0.f ? acc.w : expm1f(acc.w);
    *(float4*)&out[d * MOUT + lane * 4] = acc;
}

// ---------------------------------------------------------------------------
extern "C" void kernel_launch(void* const* d_in, const int* in_sizes, int n_in,
                              void* d_out, int out_size) {
    const float* x  = (const float*)d_in[0];
    const int*   ei = (const int*)d_in[1];
    const float* W  = (const float*)d_in[2];
    const float* aw = (const float*)d_in[3];
    float* out = (float*)d_out;

    zero2_kernel<<<(NN + 1023) / 1024, 1024>>>();
    gemm_tf32_kernel<<<(NN + BMT - 1) / BMT, 256>>>(x, W, aw);
    hist_kernel<<<(NE + 255) / 256, 256>>>(ei);
    scan1_kernel<<<NB, 256>>>();
    scan_apply_kernel<<<NB, 256>>>();
    fill_kernel<<<(NE / 4 + 255) / 256, 256>>>(ei);
    agg_kernel<<<(NN + 7) / 8, 256>>>(out);
}

// round 10
// speedup vs baseline: 1.5722x; 1.0822x over previous
#include <cuda_runtime.h>
#include <cuda_fp16.h>

#define NN   50000
#define NE   800000
#define KIN  256
#define MOUT 128
#define NH   4
#define NB   196        // ceil(NN/256)

#define BMT 128
#define BKT 32
#define XPAD 36
#define GEMM_BLOCKS ((NN + BMT - 1) / BMT)      // 391
#define HIST_BLOCKS ((NE + 1023) / 1024)        // 782

// Scratch (allocation-free rule: __device__ globals)
__device__ __align__(16) __half g_Wx_h[NN * MOUT];  // 12.8 MB fp16 Wx for agg
__device__ __align__(16) float g_ssrc[NN * NH];
__device__ __align__(16) float g_sdst[NN * NH];
__device__ int g_cnt[NN];     // zero-init at load; re-zeroed by agg each replay
__device__ int g_scan[NN];
__device__ int g_bsum[NB];
__device__ int g_off[NN + 1];
__device__ int g_cur[NN];     // zero-init at load; re-zeroed by agg each replay
__device__ int g_esrc[NE];

// ---------------------------------------------------------------------------
// Fused GEMM + histogram kernel.
// Blocks [0, GEMM_BLOCKS): tf32 mma GEMM Wx = x@W^T + fused score epilogue.
// Blocks [GEMM_BLOCKS, +HIST_BLOCKS): per-dst edge histogram (independent).
// ---------------------------------------------------------------------------
__device__ __forceinline__ unsigned f2tf32(float f) {
    unsigned u;
    asm("cvt.rna.tf32.f32 %0, %1;" : "=r"(u) : "f"(f));
    return u;
}

__device__ __forceinline__ void mma_tf32(float* c, const unsigned* a,
                                         unsigned b0, unsigned b1) {
    asm volatile(
        "mma.sync.aligned.m16n8k8.row.col.f32.tf32.tf32.f32 "
        "{%0,%1,%2,%3}, {%4,%5,%6,%7}, {%8,%9}, {%0,%1,%2,%3};"
        : "+f"(c[0]), "+f"(c[1]), "+f"(c[2]), "+f"(c[3])
        : "r"(a[0]), "r"(a[1]), "r"(a[2]), "r"(a[3]), "r"(b0), "r"(b1));
}

__global__ __launch_bounds__(256, 2)
void gemm_hist_kernel(const float* __restrict__ x,
                      const float* __restrict__ W,
                      const float* __restrict__ aw,
                      const int* __restrict__ ei) {
    __shared__ unsigned Xs[BMT * XPAD];
    __shared__ unsigned Ws[MOUT * XPAD];

    if (blockIdx.x >= GEMM_BLOCKS) {
        // ---- histogram branch: 1024 edges per block, coalesced ----
        int base = (blockIdx.x - GEMM_BLOCKS) * 1024 + threadIdx.x;
        #pragma unroll
        for (int j = 0; j < 4; j++) {
            int e = base + j * 256;
            if (e < NE) atomicAdd(&g_cnt[ei[NE + e]], 1);
        }
        return;
    }

    // ---- GEMM branch (identical to round-9 gemm_tf32_kernel) ----
    int tid  = threadIdx.x;
    int lane = tid & 31;
    int warp = tid >> 5;
    int g = lane >> 2;
    int t = lane & 3;
    int wm = warp & 3;
    int wn = warp >> 2;
    int row0 = blockIdx.x * BMT;

    float c[2][8][4];
    #pragma unroll
    for (int tm = 0; tm < 2; tm++)
        #pragma unroll
        for (int tn = 0; tn < 8; tn++)
            #pragma unroll
            for (int i = 0; i < 4; i++) c[tm][tn][i] = 0.f;

    for (int k0 = 0; k0 < KIN; k0 += BKT) {
        #pragma unroll
        for (int j = 0; j < 4; j++) {
            int idx = tid + 256 * j;
            int m   = idx >> 3;
            int kv  = (idx & 7) * 4;
            int row = row0 + m;
            float4 v = make_float4(0.f, 0.f, 0.f, 0.f);
            if (row < NN) v = *(const float4*)&x[row * KIN + k0 + kv];
            uint4 u;
            u.x = f2tf32(v.x); u.y = f2tf32(v.y);
            u.z = f2tf32(v.z); u.w = f2tf32(v.w);
            *(uint4*)&Xs[m * XPAD + kv] = u;

            float4 w4 = *(const float4*)&W[m * KIN + k0 + kv];
            uint4 uw;
            uw.x = f2tf32(w4.x); uw.y = f2tf32(w4.y);
            uw.z = f2tf32(w4.z); uw.w = f2tf32(w4.w);
            *(uint4*)&Ws[m * XPAD + kv] = uw;
        }
        __syncthreads();

        #pragma unroll
        for (int kk = 0; kk < BKT; kk += 8) {
            unsigned a[2][4];
            #pragma unroll
            for (int tm = 0; tm < 2; tm++) {
                int r = wm * 32 + tm * 16 + g;
                a[tm][0] = Xs[r * XPAD + kk + t];
                a[tm][1] = Xs[(r + 8) * XPAD + kk + t];
                a[tm][2] = Xs[r * XPAD + kk + t + 4];
                a[tm][3] = Xs[(r + 8) * XPAD + kk + t + 4];
            }
            #pragma unroll
            for (int tn = 0; tn < 8; tn++) {
                int n = wn * 64 + tn * 8 + g;
                unsigned b0 = Ws[n * XPAD + kk + t];
                unsigned b1 = Ws[n * XPAD + kk + t + 4];
                mma_tf32(c[0][tn], a[0], b0, b1);
                mma_tf32(c[1][tn], a[1], b0, b1);
            }
        }
        __syncthreads();
    }

    float as_r[4][2], ad_r[4][2];
    #pragma unroll
    for (int q = 0; q < 4; q++)
        #pragma unroll
        for (int j = 0; j < 2; j++) {
            as_r[q][j] = aw[q * 8 + 2 * t + j];
            ad_r[q][j] = aw[32 + q * 8 + 2 * t + j];
        }

    #pragma unroll
    for (int tm = 0; tm < 2; tm++)
    #pragma unroll
    for (int half = 0; half < 2; half++) {
        int row = row0 + wm * 32 + tm * 16 + half * 8 + g;

        if (row < NN) {
            #pragma unroll
            for (int tn = 0; tn < 8; tn++) {
                __half2 hv = __floats2half2_rn(c[tm][tn][half * 2],
                                               c[tm][tn][half * 2 + 1]);
                *(__half2*)&g_Wx_h[row * MOUT + wn * 64 + tn * 8 + 2 * t] = hv;
            }
        }

        #pragma unroll
        for (int hl = 0; hl < 2; hl++) {
            float ps = 0.f, pd = 0.f;
            #pragma unroll
            for (int q = 0; q < 4; q++)
                #pragma unroll
                for (int j = 0; j < 2; j++) {
                    float v = c[tm][hl * 4 + q][half * 2 + j];
                    ps += v * as_r[q][j];
                    pd += v * ad_r[q][j];
                }
            ps += __shfl_xor_sync(0xffffffffu, ps, 1);
            ps += __shfl_xor_sync(0xffffffffu, ps, 2);
            pd += __shfl_xor_sync(0xffffffffu, pd, 1);
            pd += __shfl_xor_sync(0xffffffffu, pd, 2);
            if (t == 0 && row < NN) {
                g_ssrc[row * NH + wn * 2 + hl] = ps;
                g_sdst[row * NH + wn * 2 + hl] = pd;
            }
        }
    }
}

// ---------------------------------------------------------------------------
// Scan: per-block inclusive (coalesced) + redundant block-sum apply
// ---------------------------------------------------------------------------
__global__ void scan1_kernel() {
    __shared__ int sh[256];
    int t = threadIdx.x;
    int i = blockIdx.x * 256 + t;
    int v = (i < NN) ? g_cnt[i] : 0;
    sh[t] = v;
    __syncthreads();
    #pragma unroll
    for (int ofs = 1; ofs < 256; ofs <<= 1) {
        int add = (t >= ofs) ? sh[t - ofs] : 0;
        __syncthreads();
        sh[t] += add;
        __syncthreads();
    }
    if (i < NN) g_scan[i] = sh[t];
    if (t == 255) g_bsum[blockIdx.x] = sh[255];
}

__global__ void scan_apply_kernel() {
    __shared__ int sh[256];
    int t = threadIdx.x;
    sh[t] = (t < NB) ? g_bsum[t] : 0;
    __syncthreads();
    #pragma unroll
    for (int ofs = 1; ofs < 256; ofs <<= 1) {
        int add = (t >= ofs) ? sh[t - ofs] : 0;
        __syncthreads();
        sh[t] += add;
        __syncthreads();
    }
    int base = (blockIdx.x == 0) ? 0 : sh[blockIdx.x - 1];
    int i = blockIdx.x * 256 + t;
    if (i < NN) g_off[i] = g_scan[i] - g_cnt[i] + base;
    if (i == 0) g_off[NN] = NE;
}

// 4 edges per thread for MLP on the off-load -> atomic -> store chain
__global__ void fill_kernel(const int* __restrict__ ei) {
    int b = (blockIdx.x * blockDim.x + threadIdx.x) * 4;
    if (b >= NE) return;
    int n = (NE - b < 4) ? (NE - b) : 4;
    int s[4], d[4], p[4];
    #pragma unroll
    for (int j = 0; j < 4; j++) {
        if (j < n) {
            s[j] = ei[b + j];
            d[j] = ei[NE + b + j];
        }
    }
    #pragma unroll
    for (int j = 0; j < 4; j++)
        if (j < n) p[j] = g_off[d[j]] + atomicAdd(&g_cur[d[j]], 1);
    #pragma unroll
    for (int j = 0; j < 4; j++)
        if (j < n) g_esrc[p[j]] = s[j];
}

// ---------------------------------------------------------------------------
// Aggregation: warp per dst node, smem numerator cache, warp-uniform branch.
// Also re-zeroes g_cnt/g_cur for the next graph replay (all consumers done).
// ---------------------------------------------------------------------------
#define CAP 64

__device__ __forceinline__ float lrelu_exp(float v) {
    float r = v > 0.f ? v : 0.2f * v;
    return __expf(r);
}

__global__ __launch_bounds__(256)
void agg_kernel(float* __restrict__ out) {
    __shared__ float s_al[8][CAP][NH];   // 8 KB per block

    // re-zero count/cursor arrays for the next replay (invariant keeper)
    int gid = blockIdx.x * blockDim.x + threadIdx.x;
    if (gid < NN) { g_cnt[gid] = 0; g_cur[gid] = 0; }

    int w = threadIdx.x >> 5;
    int d = blockIdx.x * 8 + w;
    if (d >= NN) return;
    int lane = threadIdx.x & 31;
    int beg = g_off[d];
    int deg = g_off[d + 1] - beg;

    float4 sd4 = *(const float4*)&g_sdst[d * 4];

    // Pass 1: per-edge numerators -> smem + denom reduction
    float4 dn = make_float4(0.f, 0.f, 0.f, 0.f);
    for (int j = lane; j < deg; j += 32) {
        int s = g_esrc[beg + j];
        float4 a = *(const float4*)&g_ssrc[s * 4];
        float4 e;
        e.x = lrelu_exp(a.x + sd4.x);
        e.y = lrelu_exp(a.y + sd4.y);
        e.z = lrelu_exp(a.z + sd4.z);
        e.w = lrelu_exp(a.w + sd4.w);
        dn.x += e.x; dn.y += e.y; dn.z += e.z; dn.w += e.w;
        if (j < CAP) *(float4*)&s_al[w][j][0] = e;
    }
    #pragma unroll
    for (int m = 16; m; m >>= 1) {
        dn.x += __shfl_xor_sync(0xffffffffu, dn.x, m);
        dn.y += __shfl_xor_sync(0xffffffffu, dn.y, m);
        dn.z += __shfl_xor_sync(0xffffffffu, dn.z, m);
        dn.w += __shfl_xor_sync(0xffffffffu, dn.w, m);
    }
    __syncwarp();

    int h = lane >> 3;
    float dnh = (h == 0) ? dn.x : (h == 1) ? dn.y : (h == 2) ? dn.z : dn.w;
    float adh = (h == 0) ? sd4.x : (h == 1) ? sd4.y : (h == 2) ? sd4.z : sd4.w;
    float invd = __fdividef(1.f, dnh + 1e-8f);

    // Pass 2: weighted fp16 gather
    float4 acc = make_float4(0.f, 0.f, 0.f, 0.f);
    if (deg <= CAP) {
        const float* al_base = &s_al[w][0][h];
        #pragma unroll 4
        for (int j = 0; j < deg; j++) {
            float al = al_base[j * NH] * invd;
            int s = g_esrc[beg + j];
            float2 raw = *(const float2*)&g_Wx_h[s * MOUT + lane * 4];
            __half2 h01 = ((__half2*)&raw)[0];
            __half2 h23 = ((__half2*)&raw)[1];
            float2 f01 = __half22float2(h01);
            float2 f23 = __half22float2(h23);
            acc.x += al * f01.x; acc.y += al * f01.y;
            acc.z += al * f23.x; acc.w += al * f23.y;
        }
    } else {
        #pragma unroll 2
        for (int j = 0; j < deg; j++) {
            int s = g_esrc[beg + j];
            float al = lrelu_exp(g_ssrc[s * 4 + h] + adh) * invd;
            float2 raw = *(const float2*)&g_Wx_h[s * MOUT + lane * 4];
            __half2 h01 = ((__half2*)&raw)[0];
            __half2 h23 = ((__half2*)&raw)[1];
            float2 f01 = __half22float2(h01);
            float2 f23 = __half22float2(h23);
            acc.x += al * f01.x; acc.y += al * f01.y;
            acc.z += al * f23.x; acc.w += al * f23.y;
        }
    }

    acc.x = acc.x > 0.f ? acc.x : expm1f(acc.x);
    acc.y = acc.y > 0.f ? acc.y : expm1f(acc.y);
    acc.z = acc.z > 0.f ? acc.z : expm1f(acc.z);
    acc.w = acc.w > 0.f ? acc.w : expm1f(acc.w);
    *(float4*)&out[d * MOUT + lane * 4] = acc;
}

// ---------------------------------------------------------------------------
extern "C" void kernel_launch(void* const* d_in, const int* in_sizes, int n_in,
                              void* d_out, int out_size) {
    const float* x  = (const float*)d_in[0];
    const int*   ei = (const int*)d_in[1];
    const float* W  = (const float*)d_in[2];
    const float* aw = (const float*)d_in[3];
    float* out = (float*)d_out;

    gemm_hist_kernel<<<GEMM_BLOCKS + HIST_BLOCKS, 256>>>(x, W, aw, ei);
    scan1_kernel<<<NB, 256>>>();
    scan_apply_kernel<<<NB, 256>>>();
    fill_kernel<<<(NE / 4 + 255) / 256, 256>>>(ei);
    agg_kernel<<<(NN + 7) / 8, 256>>>(out);
}

// round 11
// speedup vs baseline: 1.5920x; 1.0126x over previous
#include <cuda_runtime.h>
#include <cuda_fp16.h>

#define NN   50000
#define NE   800000
#define KIN  256
#define MOUT 128
#define NH   4
#define NB   196        // ceil(NN/256)

#define BMT 128
#define BKT 32
#define XPAD 36
#define GEMM_BLOCKS ((NN + BMT - 1) / BMT)      // 391
#define HIST_BLOCKS ((NE + 1023) / 1024)        // 782

// Scratch (allocation-free rule: __device__ globals)
__device__ __align__(16) __half g_Wx_h[NN * MOUT];  // 12.8 MB fp16 Wx for agg
__device__ __align__(16) float g_ssrc[NN * NH];
__device__ __align__(16) float g_sdst[NN * NH];
__device__ int g_cnt[NN];     // zero-init at load; re-zeroed by agg each replay
__device__ int g_scan[NN];
__device__ int g_bsum[NB];
__device__ int g_off[NN + 1];
__device__ int g_lpos[NE];    // per-edge position within its dst segment
__device__ int g_esrc[NE];

// ---------------------------------------------------------------------------
// Fused GEMM + histogram kernel.
// Blocks [0, GEMM_BLOCKS): tf32 mma GEMM Wx = x@W^T + fused score epilogue.
// Blocks [GEMM_BLOCKS, +HIST_BLOCKS): per-dst histogram, RECORDING the
//   atomic return as the edge's within-segment position (frees fill of atomics).
// ---------------------------------------------------------------------------
__device__ __forceinline__ unsigned f2tf32(float f) {
    unsigned u;
    asm("cvt.rna.tf32.f32 %0, %1;" : "=r"(u) : "f"(f));
    return u;
}

__device__ __forceinline__ void mma_tf32(float* c, const unsigned* a,
                                         unsigned b0, unsigned b1) {
    asm volatile(
        "mma.sync.aligned.m16n8k8.row.col.f32.tf32.tf32.f32 "
        "{%0,%1,%2,%3}, {%4,%5,%6,%7}, {%8,%9}, {%0,%1,%2,%3};"
        : "+f"(c[0]), "+f"(c[1]), "+f"(c[2]), "+f"(c[3])
        : "r"(a[0]), "r"(a[1]), "r"(a[2]), "r"(a[3]), "r"(b0), "r"(b1));
}

__global__ __launch_bounds__(256, 2)
void gemm_hist_kernel(const float* __restrict__ x,
                      const float* __restrict__ W,
                      const float* __restrict__ aw,
                      const int* __restrict__ ei) {
    __shared__ unsigned Xs[BMT * XPAD];
    __shared__ unsigned Ws[MOUT * XPAD];

    if (blockIdx.x >= GEMM_BLOCKS) {
        // ---- histogram branch: count + record local position ----
        int base = (blockIdx.x - GEMM_BLOCKS) * 1024 + threadIdx.x;
        #pragma unroll
        for (int j = 0; j < 4; j++) {
            int e = base + j * 256;
            if (e < NE) {
                int d = ei[NE + e];
                int lp = atomicAdd(&g_cnt[d], 1);
                g_lpos[e] = lp;
            }
        }
        return;
    }

    // ---- GEMM branch (identical to round-10) ----
    int tid  = threadIdx.x;
    int lane = tid & 31;
    int warp = tid >> 5;
    int g = lane >> 2;
    int t = lane & 3;
    int wm = warp & 3;
    int wn = warp >> 2;
    int row0 = blockIdx.x * BMT;

    float c[2][8][4];
    #pragma unroll
    for (int tm = 0; tm < 2; tm++)
        #pragma unroll
        for (int tn = 0; tn < 8; tn++)
            #pragma unroll
            for (int i = 0; i < 4; i++) c[tm][tn][i] = 0.f;

    for (int k0 = 0; k0 < KIN; k0 += BKT) {
        #pragma unroll
        for (int j = 0; j < 4; j++) {
            int idx = tid + 256 * j;
            int m   = idx >> 3;
            int kv  = (idx & 7) * 4;
            int row = row0 + m;
            float4 v = make_float4(0.f, 0.f, 0.f, 0.f);
            if (row < NN) v = *(const float4*)&x[row * KIN + k0 + kv];
            uint4 u;
            u.x = f2tf32(v.x); u.y = f2tf32(v.y);
            u.z = f2tf32(v.z); u.w = f2tf32(v.w);
            *(uint4*)&Xs[m * XPAD + kv] = u;

            float4 w4 = *(const float4*)&W[m * KIN + k0 + kv];
            uint4 uw;
            uw.x = f2tf32(w4.x); uw.y = f2tf32(w4.y);
            uw.z = f2tf32(w4.z); uw.w = f2tf32(w4.w);
            *(uint4*)&Ws[m * XPAD + kv] = uw;
        }
        __syncthreads();

        #pragma unroll
        for (int kk = 0; kk < BKT; kk += 8) {
            unsigned a[2][4];
            #pragma unroll
            for (int tm = 0; tm < 2; tm++) {
                int r = wm * 32 + tm * 16 + g;
                a[tm][0] = Xs[r * XPAD + kk + t];
                a[tm][1] = Xs[(r + 8) * XPAD + kk + t];
                a[tm][2] = Xs[r * XPAD + kk + t + 4];
                a[tm][3] = Xs[(r + 8) * XPAD + kk + t + 4];
            }
            #pragma unroll
            for (int tn = 0; tn < 8; tn++) {
                int n = wn * 64 + tn * 8 + g;
                unsigned b0 = Ws[n * XPAD + kk + t];
                unsigned b1 = Ws[n * XPAD + kk + t + 4];
                mma_tf32(c[0][tn], a[0], b0, b1);
                mma_tf32(c[1][tn], a[1], b0, b1);
            }
        }
        __syncthreads();
    }

    float as_r[4][2], ad_r[4][2];
    #pragma unroll
    for (int q = 0; q < 4; q++)
        #pragma unroll
        for (int j = 0; j < 2; j++) {
            as_r[q][j] = aw[q * 8 + 2 * t + j];
            ad_r[q][j] = aw[32 + q * 8 + 2 * t + j];
        }

    #pragma unroll
    for (int tm = 0; tm < 2; tm++)
    #pragma unroll
    for (int half = 0; half < 2; half++) {
        int row = row0 + wm * 32 + tm * 16 + half * 8 + g;

        if (row < NN) {
            #pragma unroll
            for (int tn = 0; tn < 8; tn++) {
                __half2 hv = __floats2half2_rn(c[tm][tn][half * 2],
                                               c[tm][tn][half * 2 + 1]);
                *(__half2*)&g_Wx_h[row * MOUT + wn * 64 + tn * 8 + 2 * t] = hv;
            }
        }

        #pragma unroll
        for (int hl = 0; hl < 2; hl++) {
            float ps = 0.f, pd = 0.f;
            #pragma unroll
            for (int q = 0; q < 4; q++)
                #pragma unroll
                for (int j = 0; j < 2; j++) {
                    float v = c[tm][hl * 4 + q][half * 2 + j];
                    ps += v * as_r[q][j];
                    pd += v * ad_r[q][j];
                }
            ps += __shfl_xor_sync(0xffffffffu, ps, 1);
            ps += __shfl_xor_sync(0xffffffffu, ps, 2);
            pd += __shfl_xor_sync(0xffffffffu, pd, 1);
            pd += __shfl_xor_sync(0xffffffffu, pd, 2);
            if (t == 0 && row < NN) {
                g_ssrc[row * NH + wn * 2 + hl] = ps;
                g_sdst[row * NH + wn * 2 + hl] = pd;
            }
        }
    }
}

// ---------------------------------------------------------------------------
// Scan: per-block inclusive (coalesced) + redundant block-sum apply
// ---------------------------------------------------------------------------
__global__ void scan1_kernel() {
    __shared__ int sh[256];
    int t = threadIdx.x;
    int i = blockIdx.x * 256 + t;
    int v = (i < NN) ? g_cnt[i] : 0;
    sh[t] = v;
    __syncthreads();
    #pragma unroll
    for (int ofs = 1; ofs < 256; ofs <<= 1) {
        int add = (t >= ofs) ? sh[t - ofs] : 0;
        __syncthreads();
        sh[t] += add;
        __syncthreads();
    }
    if (i < NN) g_scan[i] = sh[t];
    if (t == 255) g_bsum[blockIdx.x] = sh[255];
}

__global__ void scan_apply_kernel() {
    __shared__ int sh[256];
    int t = threadIdx.x;
    sh[t] = (t < NB) ? g_bsum[t] : 0;
    __syncthreads();
    #pragma unroll
    for (int ofs = 1; ofs < 256; ofs <<= 1) {
        int add = (t >= ofs) ? sh[t - ofs] : 0;
        __syncthreads();
        sh[t] += add;
        __syncthreads();
    }
    int base = (blockIdx.x == 0) ? 0 : sh[blockIdx.x - 1];
    int i = blockIdx.x * 256 + t;
    if (i < NN) g_off[i] = g_scan[i] - g_cnt[i] + base;
    if (i == 0) g_off[NN] = NE;
}

// Atomic-free fill: position = segment offset + recorded local position.
__global__ void fill_kernel(const int* __restrict__ ei) {
    int b = (blockIdx.x * blockDim.x + threadIdx.x) * 4;
    if (b >= NE) return;
    int n = (NE - b < 4) ? (NE - b) : 4;
    int s[4], d[4], lp[4];
    #pragma unroll
    for (int j = 0; j < 4; j++) {
        if (j < n) {
            s[j]  = ei[b + j];
            d[j]  = ei[NE + b + j];
            lp[j] = g_lpos[b + j];
        }
    }
    #pragma unroll
    for (int j = 0; j < 4; j++)
        if (j < n) g_esrc[g_off[d[j]] + lp[j]] = s[j];
}

// ---------------------------------------------------------------------------
// Aggregation: single pass. out = (Σ e_exp·Wx[src]) / (Σ e_exp + 1e-8), ELU.
// Each lane owns 4 cols of one head; its den accumulates over ALL edges, so
// no warp reduction, no smem, no second pass. Re-zeroes g_cnt for next replay.
// ---------------------------------------------------------------------------
__device__ __forceinline__ float lrelu_exp(float v) {
    float r = v > 0.f ? v : 0.2f * v;
    return __expf(r);
}

__global__ __launch_bounds__(256)
void agg_kernel(float* __restrict__ out) {
    // re-zero count array for the next replay (all consumers done)
    int gid = blockIdx.x * blockDim.x + threadIdx.x;
    if (gid < NN) g_cnt[gid] = 0;

    int d = blockIdx.x * 8 + (threadIdx.x >> 5);
    if (d >= NN) return;
    int lane = threadIdx.x & 31;
    int h = lane >> 3;
    int beg = g_off[d];
    int deg = g_off[d + 1] - beg;

    float adh = g_sdst[d * 4 + h];

    float4 acc = make_float4(0.f, 0.f, 0.f, 0.f);
    float den = 0.f;
    #pragma unroll 4
    for (int j = 0; j < deg; j++) {
        int s = g_esrc[beg + j];                         // warp-uniform
        float e = lrelu_exp(g_ssrc[s * 4 + h] + adh);    // 8-lane broadcast load
        float2 raw = *(const float2*)&g_Wx_h[s * MOUT + lane * 4];
        __half2 h01 = ((__half2*)&raw)[0];
        __half2 h23 = ((__half2*)&raw)[1];
        float2 f01 = __half22float2(h01);
        float2 f23 = __half22float2(h23);
        acc.x += e * f01.x; acc.y += e * f01.y;
        acc.z += e * f23.x; acc.w += e * f23.y;
        den += e;
    }

    float invd = __fdividef(1.f, den + 1e-8f);
    acc.x *= invd; acc.y *= invd; acc.z *= invd; acc.w *= invd;

    acc.x = acc.x > 0.f ? acc.x : expm1f(acc.x);
    acc.y = acc.y > 0.f ? acc.y : expm1f(acc.y);
    acc.z = acc.z > 0.f ? acc.z : expm1f(acc.z);
    acc.w = acc.w > 0.f ? acc.w : expm1f(acc.w);
    *(float4*)&out[d * MOUT + lane * 4] = acc;
}

// ---------------------------------------------------------------------------
extern "C" void kernel_launch(void* const* d_in, const int* in_sizes, int n_in,
                              void* d_out, int out_size) {
    const float* x  = (const float*)d_in[0];
    const int*   ei = (const int*)d_in[1];
    const float* W  = (const float*)d_in[2];
    const float* aw = (const float*)d_in[3];
    float* out = (float*)d_out;

    gemm_hist_kernel<<<GEMM_BLOCKS + HIST_BLOCKS, 256>>>(x, W, aw, ei);
    scan1_kernel<<<NB, 256>>>();
    scan_apply_kernel<<<NB, 256>>>();
    fill_kernel<<<(NE / 4 + 255) / 256, 256>>>(ei);
    agg_kernel<<<(NN + 7) / 8, 256>>>(out);
}

// round 12
// speedup vs baseline: 1.6668x; 1.0470x over previous
#include <cuda_runtime.h>
#include <cuda_fp16.h>

#define NN   50000
#define NE   800000
#define KIN  256
#define MOUT 128
#define NH   4
#define NB   196        // ceil(NN/256)

#define BMT 128
#define BKT 32
#define XPAD 36
#define GEMM_BLOCKS ((NN + BMT - 1) / BMT)      // 391
#define HIST_BLOCKS ((NE + 1023) / 1024)        // 782

// Scratch (allocation-free rule: __device__ globals)
__device__ __align__(16) __half g_Wx_h[NN * MOUT];  // 12.8 MB fp16 Wx for agg
__device__ __align__(16) float g_ssrc[NN * NH];
__device__ __align__(16) float g_sdst[NN * NH];
__device__ int g_cnt[NN];     // zero-init at load; re-zeroed by agg each replay
__device__ int g_scan[NN];
__device__ int g_bsum[NB];
__device__ int g_off[NN + 1];
__device__ int g_lpos[NE];    // per-edge position within its dst segment
__device__ int g_esrc[NE];

// ---------------------------------------------------------------------------
// Fused GEMM + histogram kernel.
// Blocks [0, GEMM_BLOCKS): tf32 mma GEMM Wx = x@W^T + fused score epilogue.
// Blocks [GEMM_BLOCKS, +HIST_BLOCKS): per-dst histogram, recording the atomic
//   return as the edge's within-segment position (makes fill atomic-free).
// ---------------------------------------------------------------------------
__device__ __forceinline__ unsigned f2tf32(float f) {
    unsigned u;
    asm("cvt.rna.tf32.f32 %0, %1;" : "=r"(u) : "f"(f));
    return u;
}

__device__ __forceinline__ void mma_tf32(float* c, const unsigned* a,
                                         unsigned b0, unsigned b1) {
    asm volatile(
        "mma.sync.aligned.m16n8k8.row.col.f32.tf32.tf32.f32 "
        "{%0,%1,%2,%3}, {%4,%5,%6,%7}, {%8,%9}, {%0,%1,%2,%3};"
        : "+f"(c[0]), "+f"(c[1]), "+f"(c[2]), "+f"(c[3])
        : "r"(a[0]), "r"(a[1]), "r"(a[2]), "r"(a[3]), "r"(b0), "r"(b1));
}

__global__ __launch_bounds__(256, 2)
void gemm_hist_kernel(const float* __restrict__ x,
                      const float* __restrict__ W,
                      const float* __restrict__ aw,
                      const int* __restrict__ ei) {
    __shared__ unsigned Xs[BMT * XPAD];
    __shared__ unsigned Ws[MOUT * XPAD];

    if (blockIdx.x >= GEMM_BLOCKS) {
        // ---- histogram branch: count + record local position ----
        int base = (blockIdx.x - GEMM_BLOCKS) * 1024 + threadIdx.x;
        #pragma unroll
        for (int j = 0; j < 4; j++) {
            int e = base + j * 256;
            if (e < NE) {
                int d = ei[NE + e];
                int lp = atomicAdd(&g_cnt[d], 1);
                g_lpos[e] = lp;
            }
        }
        return;
    }

    // ---- GEMM branch ----
    int tid  = threadIdx.x;
    int lane = tid & 31;
    int warp = tid >> 5;
    int g = lane >> 2;
    int t = lane & 3;
    int wm = warp & 3;
    int wn = warp >> 2;
    int row0 = blockIdx.x * BMT;

    float c[2][8][4];
    #pragma unroll
    for (int tm = 0; tm < 2; tm++)
        #pragma unroll
        for (int tn = 0; tn < 8; tn++)
            #pragma unroll
            for (int i = 0; i < 4; i++) c[tm][tn][i] = 0.f;

    for (int k0 = 0; k0 < KIN; k0 += BKT) {
        #pragma unroll
        for (int j = 0; j < 4; j++) {
            int idx = tid + 256 * j;
            int m   = idx >> 3;
            int kv  = (idx & 7) * 4;
            int row = row0 + m;
            float4 v = make_float4(0.f, 0.f, 0.f, 0.f);
            if (row < NN) v = *(const float4*)&x[row * KIN + k0 + kv];
            uint4 u;
            u.x = f2tf32(v.x); u.y = f2tf32(v.y);
            u.z = f2tf32(v.z); u.w = f2tf32(v.w);
            *(uint4*)&Xs[m * XPAD + kv] = u;

            float4 w4 = *(const float4*)&W[m * KIN + k0 + kv];
            uint4 uw;
            uw.x = f2tf32(w4.x); uw.y = f2tf32(w4.y);
            uw.z = f2tf32(w4.z); uw.w = f2tf32(w4.w);
            *(uint4*)&Ws[m * XPAD + kv] = uw;
        }
        __syncthreads();

        #pragma unroll
        for (int kk = 0; kk < BKT; kk += 8) {
            unsigned a[2][4];
            #pragma unroll
            for (int tm = 0; tm < 2; tm++) {
                int r = wm * 32 + tm * 16 + g;
                a[tm][0] = Xs[r * XPAD + kk + t];
                a[tm][1] = Xs[(r + 8) * XPAD + kk + t];
                a[tm][2] = Xs[r * XPAD + kk + t + 4];
                a[tm][3] = Xs[(r + 8) * XPAD + kk + t + 4];
            }
            #pragma unroll
            for (int tn = 0; tn < 8; tn++) {
                int n = wn * 64 + tn * 8 + g;
                unsigned b0 = Ws[n * XPAD + kk + t];
                unsigned b1 = Ws[n * XPAD + kk + t + 4];
                mma_tf32(c[0][tn], a[0], b0, b1);
                mma_tf32(c[1][tn], a[1], b0, b1);
            }
        }
        __syncthreads();
    }

    float as_r[4][2], ad_r[4][2];
    #pragma unroll
    for (int q = 0; q < 4; q++)
        #pragma unroll
        for (int j = 0; j < 2; j++) {
            as_r[q][j] = aw[q * 8 + 2 * t + j];
            ad_r[q][j] = aw[32 + q * 8 + 2 * t + j];
        }

    #pragma unroll
    for (int tm = 0; tm < 2; tm++)
    #pragma unroll
    for (int half = 0; half < 2; half++) {
        int row = row0 + wm * 32 + tm * 16 + half * 8 + g;

        if (row < NN) {
            #pragma unroll
            for (int tn = 0; tn < 8; tn++) {
                __half2 hv = __floats2half2_rn(c[tm][tn][half * 2],
                                               c[tm][tn][half * 2 + 1]);
                *(__half2*)&g_Wx_h[row * MOUT + wn * 64 + tn * 8 + 2 * t] = hv;
            }
        }

        #pragma unroll
        for (int hl = 0; hl < 2; hl++) {
            float ps = 0.f, pd = 0.f;
            #pragma unroll
            for (int q = 0; q < 4; q++)
                #pragma unroll
                for (int j = 0; j < 2; j++) {
                    float v = c[tm][hl * 4 + q][half * 2 + j];
                    ps += v * as_r[q][j];
                    pd += v * ad_r[q][j];
                }
            ps += __shfl_xor_sync(0xffffffffu, ps, 1);
            ps += __shfl_xor_sync(0xffffffffu, ps, 2);
            pd += __shfl_xor_sync(0xffffffffu, pd, 1);
            pd += __shfl_xor_sync(0xffffffffu, pd, 2);
            if (t == 0 && row < NN) {
                g_ssrc[row * NH + wn * 2 + hl] = ps;
                g_sdst[row * NH + wn * 2 + hl] = pd;
            }
        }
    }
}

// ---------------------------------------------------------------------------
// Scan: per-block inclusive (coalesced) + redundant block-sum apply
// ---------------------------------------------------------------------------
__global__ void scan1_kernel() {
    __shared__ int sh[256];
    int t = threadIdx.x;
    int i = blockIdx.x * 256 + t;
    int v = (i < NN) ? g_cnt[i] : 0;
    sh[t] = v;
    __syncthreads();
    #pragma unroll
    for (int ofs = 1; ofs < 256; ofs <<= 1) {
        int add = (t >= ofs) ? sh[t - ofs] : 0;
        __syncthreads();
        sh[t] += add;
        __syncthreads();
    }
    if (i < NN) g_scan[i] = sh[t];
    if (t == 255) g_bsum[blockIdx.x] = sh[255];
}

__global__ void scan_apply_kernel() {
    __shared__ int sh[256];
    int t = threadIdx.x;
    sh[t] = (t < NB) ? g_bsum[t] : 0;
    __syncthreads();
    #pragma unroll
    for (int ofs = 1; ofs < 256; ofs <<= 1) {
        int add = (t >= ofs) ? sh[t - ofs] : 0;
        __syncthreads();
        sh[t] += add;
        __syncthreads();
    }
    int base = (blockIdx.x == 0) ? 0 : sh[blockIdx.x - 1];
    int i = blockIdx.x * 256 + t;
    if (i < NN) g_off[i] = g_scan[i] - g_cnt[i] + base;
    if (i == 0) g_off[NN] = NE;
}

// Atomic-free fill, 8 edges/thread for MLP.
__global__ void fill_kernel(const int* __restrict__ ei) {
    int b = (blockIdx.x * blockDim.x + threadIdx.x) * 8;
    if (b >= NE) return;
    int n = (NE - b < 8) ? (NE - b) : 8;
    int s[8], d[8], lp[8];
    #pragma unroll
    for (int j = 0; j < 8; j++) {
        if (j < n) {
            s[j]  = ei[b + j];
            d[j]  = ei[NE + b + j];
            lp[j] = g_lpos[b + j];
        }
    }
    #pragma unroll
    for (int j = 0; j < 8; j++)
        if (j < n) g_esrc[g_off[d[j]] + lp[j]] = s[j];
}

// ---------------------------------------------------------------------------
// Aggregation (round-10 best): warp per dst node, two-pass, smem numerator
// cache, warp-uniform fast/slow branch. Re-zeroes g_cnt for next replay.
// ---------------------------------------------------------------------------
#define CAP 64

__device__ __forceinline__ float lrelu_exp(float v) {
    float r = v > 0.f ? v : 0.2f * v;
    return __expf(r);
}

__global__ __launch_bounds__(256)
void agg_kernel(float* __restrict__ out) {
    __shared__ float s_al[8][CAP][NH];   // 8 KB per block

    // re-zero count array for the next replay (all consumers done)
    int gid = blockIdx.x * blockDim.x + threadIdx.x;
    if (gid < NN) g_cnt[gid] = 0;

    int w = threadIdx.x >> 5;
    int d = blockIdx.x * 8 + w;
    if (d >= NN) return;
    int lane = threadIdx.x & 31;
    int beg = g_off[d];
    int deg = g_off[d + 1] - beg;

    float4 sd4 = *(const float4*)&g_sdst[d * 4];

    // Pass 1: per-edge numerators -> smem + denom reduction
    float4 dn = make_float4(0.f, 0.f, 0.f, 0.f);
    for (int j = lane; j < deg; j += 32) {
        int s = g_esrc[beg + j];
        float4 a = *(const float4*)&g_ssrc[s * 4];
        float4 e;
        e.x = lrelu_exp(a.x + sd4.x);
        e.y = lrelu_exp(a.y + sd4.y);
        e.z = lrelu_exp(a.z + sd4.z);
        e.w = lrelu_exp(a.w + sd4.w);
        dn.x += e.x; dn.y += e.y; dn.z += e.z; dn.w += e.w;
        if (j < CAP) *(float4*)&s_al[w][j][0] = e;
    }
    #pragma unroll
    for (int m = 16; m; m >>= 1) {
        dn.x += __shfl_xor_sync(0xffffffffu, dn.x, m);
        dn.y += __shfl_xor_sync(0xffffffffu, dn.y, m);
        dn.z += __shfl_xor_sync(0xffffffffu, dn.z, m);
        dn.w += __shfl_xor_sync(0xffffffffu, dn.w, m);
    }
    __syncwarp();

    int h = lane >> 3;
    float dnh = (h == 0) ? dn.x : (h == 1) ? dn.y : (h == 2) ? dn.z : dn.w;
    float adh = (h == 0) ? sd4.x : (h == 1) ? sd4.y : (h == 2) ? sd4.z : sd4.w;
    float invd = __fdividef(1.f, dnh + 1e-8f);

    // Pass 2: weighted fp16 gather
    float4 acc = make_float4(0.f, 0.f, 0.f, 0.f);
    if (deg <= CAP) {
        const float* al_base = &s_al[w][0][h];
        #pragma unroll 4
        for (int j = 0; j < deg; j++) {
            float al = al_base[j * NH] * invd;
            int s = g_esrc[beg + j];
            float2 raw = *(const float2*)&g_Wx_h[s * MOUT + lane * 4];
            __half2 h01 = ((__half2*)&raw)[0];
            __half2 h23 = ((__half2*)&raw)[1];
            float2 f01 = __half22float2(h01);
            float2 f23 = __half22float2(h23);
            acc.x += al * f01.x; acc.y += al * f01.y;
            acc.z += al * f23.x; acc.w += al * f23.y;
        }
    } else {
        #pragma unroll 2
        for (int j = 0; j < deg; j++) {
            int s = g_esrc[beg + j];
            float al = lrelu_exp(g_ssrc[s * 4 + h] + adh) * invd;
            float2 raw = *(const float2*)&g_Wx_h[s * MOUT + lane * 4];
            __half2 h01 = ((__half2*)&raw)[0];
            __half2 h23 = ((__half2*)&raw)[1];
            float2 f01 = __half22float2(h01);
            float2 f23 = __half22float2(h23);
            acc.x += al * f01.x; acc.y += al * f01.y;
            acc.z += al * f23.x; acc.w += al * f23.y;
        }
    }

    acc.x = acc.x > 0.f ? acc.x : expm1f(acc.x);
    acc.y = acc.y > 0.f ? acc.y : expm1f(acc.y);
    acc.z = acc.z > 0.f ? acc.z : expm1f(acc.z);
    acc.w = acc.w > 0.f ? acc.w : expm1f(acc.w);
    *(float4*)&out[d * MOUT + lane * 4] = acc;
}

// ---------------------------------------------------------------------------
extern "C" void kernel_launch(void* const* d_in, const int* in_sizes, int n_in,
                              void* d_out, int out_size) {
    const float* x  = (const float*)d_in[0];
    const int*   ei = (const int*)d_in[1];
    const float* W  = (const float*)d_in[2];
    const float* aw = (const float*)d_in[3];
    float* out = (float*)d_out;

    gemm_hist_kernel<<<GEMM_BLOCKS + HIST_BLOCKS, 256>>>(x, W, aw, ei);
    scan1_kernel<<<NB, 256>>>();
    scan_apply_kernel<<<NB, 256>>>();
    fill_kernel<<<(NE / 8 + 255) / 256, 256>>>(ei);
    agg_kernel<<<(NN + 7) / 8, 256>>>(out);
}